// round 14
// baseline (speedup 1.0000x reference)
#include <cuda_runtime.h>
#include <cuda_bf16.h>
#include <math.h>

typedef unsigned int u32;
typedef unsigned long long u64;

// ---------------- problem constants ----------------
#define B_   2
#define S_   2048
#define H_   2048
#define NH_  16
#define DH_  128
#define E_   6
#define R_   16
#define T_   (B_ * S_)            // 4096 tokens
#define SCALING_ 8.0f
#define INV_SQRT_DH 0.08838834764831845f

// narrow tile: 128 rows x 32 bf16 = 64B/row, XOR-swizzled. 8KB per plane.
#define PLB 8192
#define STG_B (4 * PLB)           // Ahi, Alo, Bhi, Blo = 32KB
#define NSTG 3
#define SMEM_SZ (NSTG * STG_B)    // 96KB
// wide tile: B is 256 rows -> 16KB per plane
#define PLB2 16384
#define STG2 (2 * PLB + 2 * PLB2) // 48KB
#define SMEM2 (NSTG * STG2)       // 144KB

// ---------------- scratch: fp32 ----------------
__device__ float g_vt[T_ * H_];        // V untransposed [t][n] (atomic accum)
__device__ float g_L[B_ * NH_ * S_];   // unnormalized softmax row sums
__device__ float g_xacat[T_ * 128];
__device__ float g_xao[T_ * 128];
__device__ float g_wcat[128 * H_];
__device__ float g_wcat2[128 * H_];
__device__ int   g_list_v[E_ * T_];
__device__ int   g_list_o[E_ * T_];
__device__ int   g_cnt_v[E_];
__device__ int   g_cnt_o[E_];
__device__ float g_wslot_v[T_ * 2];
__device__ float g_wslot_o[T_ * 2];

// ---------------- scratch: bf16 hi/lo planes (u32 = 2 bf16) ----------------
#define PT (T_ * H_ / 2)
#define PW (H_ * H_ / 2)
#define PE (E_ * H_ * H_ / 2)
#define PC (128 * H_ / 2)
__device__ u32 g_xs_h[PT],  g_xs_l[PT];
__device__ u32 g_qs_h[PT],  g_qs_l[PT];
__device__ u32 g_ks_h[PT],  g_ks_l[PT];
__device__ u32 g_cts_h[PT], g_cts_l[PT];
__device__ u32 g_vts_h[PT], g_vts_l[PT];   // V transposed planes [b*H+n][S]
__device__ u32 g_Ps_h[(size_t)B_ * NH_ * S_ * S_ / 2];
__device__ u32 g_Ps_l[(size_t)B_ * NH_ * S_ * S_ / 2];
__device__ u32 g_wqs_h[PW], g_wqs_l[PW];
__device__ u32 g_wks_h[PW], g_wks_l[PW];
__device__ u32 g_vbs_h[PE], g_vbs_l[PE];
__device__ u32 g_obs_h[PE], g_obs_l[PE];
__device__ u32 g_wcs_h[PC], g_wcs_l[PC];
__device__ u32 g_wcs2_h[PC], g_wcs2_l[PC];

// ---------------- helpers ----------------
__device__ __forceinline__ u32 s2u(const void* p) {
    u32 a;
    asm("{ .reg .u64 t; cvta.to.shared.u64 t, %1; cvt.u32.u64 %0, t; }" : "=r"(a) : "l"(p));
    return a;
}
__device__ __forceinline__ u32 pack_bf2(float a, float b) {
    __nv_bfloat162 t = __floats2bfloat162_rn(a, b);
    return *reinterpret_cast<u32*>(&t);
}
__device__ __forceinline__ void split4(float4 v, u32& h0, u32& h1, u32& l0, u32& l1) {
    __nv_bfloat162 p0 = __floats2bfloat162_rn(v.x, v.y);
    __nv_bfloat162 p1 = __floats2bfloat162_rn(v.z, v.w);
    h0 = *reinterpret_cast<u32*>(&p0);
    h1 = *reinterpret_cast<u32*>(&p1);
    l0 = pack_bf2(v.x - __low2float(p0), v.y - __high2float(p0));
    l1 = pack_bf2(v.z - __low2float(p1), v.w - __high2float(p1));
}
__device__ __forceinline__ void split2(float a, float b, u32& h, u32& l) {
    __nv_bfloat162 p = __floats2bfloat162_rn(a, b);
    h = *reinterpret_cast<u32*>(&p);
    l = pack_bf2(a - __low2float(p), b - __high2float(p));
}
__device__ __forceinline__ void mma_bf16(float* c, u32 a0, u32 a1, u32 a2, u32 a3, u32 b0, u32 b1) {
    asm volatile(
        "mma.sync.aligned.m16n8k16.row.col.f32.bf16.bf16.f32 "
        "{%0,%1,%2,%3}, {%4,%5,%6,%7}, {%8,%9}, {%0,%1,%2,%3};"
        : "+f"(c[0]), "+f"(c[1]), "+f"(c[2]), "+f"(c[3])
        : "r"(a0), "r"(a1), "r"(a2), "r"(a3), "r"(b0), "r"(b1));
}
__device__ __forceinline__ void ldsm4(u32* r, u32 a) {
    asm volatile("ldmatrix.sync.aligned.m8n8.x4.shared.b16 {%0,%1,%2,%3}, [%4];"
        : "=r"(r[0]), "=r"(r[1]), "=r"(r[2]), "=r"(r[3]) : "r"(a));
}
__device__ __forceinline__ void cpa16(u32 dst, const void* src) {
    asm volatile("cp.async.ca.shared.global [%0], [%1], 16;" :: "r"(dst), "l"(src));
}
#define CPA_COMMIT() asm volatile("cp.async.commit_group;" ::: "memory")
#define CPA_WAIT1()  asm volatile("cp.async.wait_group 1;" ::: "memory")
#define CPA_WAIT0()  asm volatile("cp.async.wait_group 0;" ::: "memory")
// XOR swizzle: row 64B, seg = 16B chunk idx (0..3)
__device__ __forceinline__ u32 swb(int row, int seg) {
    return (u32)(row * 64 + ((seg ^ ((row >> 1) & 3)) * 16));
}

// one k16 step, 128x128 tile (3-term bf16 split), stage base = stg
__device__ __forceinline__ void compute_k16(u32 stg, int ks, int wm, int wn, int lane,
                                            float (&acc)[4][4][4]) {
    int j = lane >> 3, r7 = lane & 7;
    int rowA = wm * 64 + (j & 1) * 8 + r7;
    int segA = ks * 2 + (j >> 1);
    u32 aH = stg + swb(rowA, segA);
    u32 aL = aH + PLB;
    int rowB = wn * 32 + (j >> 1) * 8 + r7;
    int segB = ks * 2 + (j & 1);
    u32 bH = stg + 2 * PLB + swb(rowB, segB);
    u32 bL = bH + PLB;

    u32 bh[2][4], bl[2][4], am[4][4];
    ldsm4(bh[0], bH); ldsm4(bh[1], bH + 1024);
    ldsm4(bl[0], bL); ldsm4(bl[1], bL + 1024);
#pragma unroll
    for (int mf = 0; mf < 4; mf++) ldsm4(am[mf], aH + mf * 1024);
#pragma unroll
    for (int mf = 0; mf < 4; mf++)
#pragma unroll
        for (int nf = 0; nf < 4; nf++) {
            const u32* b = &bh[nf >> 1][(nf & 1) * 2];
            mma_bf16(acc[mf][nf], am[mf][0], am[mf][1], am[mf][2], am[mf][3], b[0], b[1]);
        }
#pragma unroll
    for (int mf = 0; mf < 4; mf++)
#pragma unroll
        for (int nf = 0; nf < 4; nf++) {
            const u32* b = &bl[nf >> 1][(nf & 1) * 2];
            mma_bf16(acc[mf][nf], am[mf][0], am[mf][1], am[mf][2], am[mf][3], b[0], b[1]);
        }
#pragma unroll
    for (int mf = 0; mf < 4; mf++) ldsm4(am[mf], aL + mf * 1024);
#pragma unroll
    for (int mf = 0; mf < 4; mf++)
#pragma unroll
        for (int nf = 0; nf < 4; nf++) {
            const u32* b = &bh[nf >> 1][(nf & 1) * 2];
            mma_bf16(acc[mf][nf], am[mf][0], am[mf][1], am[mf][2], am[mf][3], b[0], b[1]);
        }
}

// one k16 step, 128x256 tile: A planes at stg/+PLB, B planes at stg+2*PLB/+PLB2
__device__ __forceinline__ void compute_k16_w(u32 stg, int ks, int wm, int wn, int lane,
                                              float (&acc)[4][8][4]) {
    int j = lane >> 3, r7 = lane & 7;
    int rowA = wm * 64 + (j & 1) * 8 + r7;
    int segA = ks * 2 + (j >> 1);
    u32 aH = stg + swb(rowA, segA);
    u32 aL = aH + PLB;
    u32 bB = stg + 2 * PLB;
    int segB = ks * 2 + (j & 1);
    int rowB0 = wn * 64 + (j >> 1) * 8 + r7;

    u32 bh[4][4], bl[4][4], am[4][4];
#pragma unroll
    for (int c = 0; c < 4; c++) {
        u32 ba = bB + swb(rowB0 + c * 16, segB);
        ldsm4(bh[c], ba);
        ldsm4(bl[c], ba + PLB2);
    }
#pragma unroll
    for (int mf = 0; mf < 4; mf++) ldsm4(am[mf], aH + mf * 1024);
#pragma unroll
    for (int mf = 0; mf < 4; mf++)
#pragma unroll
        for (int nf = 0; nf < 8; nf++) {
            const u32* b = &bh[nf >> 1][(nf & 1) * 2];
            mma_bf16(acc[mf][nf], am[mf][0], am[mf][1], am[mf][2], am[mf][3], b[0], b[1]);
        }
#pragma unroll
    for (int mf = 0; mf < 4; mf++)
#pragma unroll
        for (int nf = 0; nf < 8; nf++) {
            const u32* b = &bl[nf >> 1][(nf & 1) * 2];
            mma_bf16(acc[mf][nf], am[mf][0], am[mf][1], am[mf][2], am[mf][3], b[0], b[1]);
        }
#pragma unroll
    for (int mf = 0; mf < 4; mf++) ldsm4(am[mf], aL + mf * 1024);
#pragma unroll
    for (int mf = 0; mf < 4; mf++)
#pragma unroll
        for (int nf = 0; nf < 8; nf++) {
            const u32* b = &bh[nf >> 1][(nf & 1) * 2];
            mma_bf16(acc[mf][nf], am[mf][0], am[mf][1], am[mf][2], am[mf][3], b[0], b[1]);
        }
}

// ---------------- kernels ----------------
enum { M_XA = 1, M_MOE = 2, M_SCORES = 4, M_CTX = 5, M_QKV = 6 };

typedef const __nv_bfloat16 cbf;

// ======== narrow (128x128): XA / SCORES / CTX ========
template <int MODE>
__global__ void __launch_bounds__(256) tc_gemm(
    cbf* Ah_, cbf* Al_, cbf* Bh_, cbf* Bl_,
    float* __restrict__ Cf, u32* __restrict__ Ch, u32* __restrict__ Cl,
    const float* __restrict__ gw) {
    extern __shared__ __align__(16) unsigned char dsm[];
    __shared__ float s_row[128];

    int tid = threadIdx.x;
    int m0 = blockIdx.y * 128, n0 = blockIdx.x * 128, z = blockIdx.z;

    cbf *pAh, *pAl, *pBh, *pBl;
    long lda, ldb, ldc = 0;
    int K;
    size_t coff = 0;

    if constexpr (MODE == M_XA) {
        pAh = Ah_ + (size_t)m0 * H_; pAl = Al_ + (size_t)m0 * H_;
        pBh = Bh_; pBl = Bl_;
        coff = (size_t)m0 * 128;
        lda = ldb = H_; ldc = 128; K = H_;
    } else if constexpr (MODE == M_SCORES) {
        int b = z >> 4, h = z & 15;
        size_t ao = ((size_t)b * S_ + m0) * H_ + h * DH_;
        size_t bo = ((size_t)b * S_ + n0) * H_ + h * DH_;
        pAh = Ah_ + ao; pAl = Al_ + ao;
        pBh = Bh_ + bo; pBl = Bl_ + bo;
        coff = (size_t)z * S_ * S_ + (size_t)m0 * S_ + n0;
        lda = ldb = H_; ldc = S_; K = DH_;
    } else {  // M_CTX
        size_t ao = (size_t)z * S_ * S_ + (size_t)m0 * S_;
        size_t bo = (size_t)z * DH_ * S_;
        pAh = Ah_ + ao; pAl = Al_ + ao;
        pBh = Bh_ + bo; pBl = Bl_ + bo;
        int b = z >> 4, h = z & 15;
        coff = ((size_t)b * S_ + m0) * H_ + h * DH_;
        lda = S_; ldb = S_; ldc = H_; K = S_;
    }

    if constexpr (MODE == M_SCORES) {
        if (tid < 128) s_row[tid] = (1.0f - gw[(size_t)(z >> 4) * S_ + n0 + tid]) * (-10000.0f);
    }
    if constexpr (MODE == M_CTX) {
        if (tid < 128) s_row[tid] = 1.0f / g_L[(size_t)z * S_ + m0 + tid];
    }

    int wid = tid >> 5, lane = tid & 31;
    int wm = wid & 1, wn = wid >> 1, g = lane >> 2, tig = lane & 3;
    u32 smb = s2u(dsm);

    int cr = tid >> 2, seg = tid & 3;
    cbf* sAh0 = pAh + (long)cr * lda + seg * 8;
    cbf* sAh1 = pAh + (long)(cr + 64) * lda + seg * 8;
    cbf* sAl0 = pAl + (long)cr * lda + seg * 8;
    cbf* sAl1 = pAl + (long)(cr + 64) * lda + seg * 8;
    cbf* sBh0 = pBh + (long)cr * ldb + seg * 8;
    cbf* sBh1 = pBh + (long)(cr + 64) * ldb + seg * 8;
    cbf* sBl0 = pBl + (long)cr * ldb + seg * 8;
    cbf* sBl1 = pBl + (long)(cr + 64) * ldb + seg * 8;
    u32 d0 = swb(cr, seg), d1 = swb(cr + 64, seg);

#define LOAD_STAGE(s, ktE) do { u32 st_ = smb + (s) * STG_B; int k_ = (ktE); \
    cpa16(st_ + d0, sAh0 + k_);            cpa16(st_ + d1, sAh1 + k_); \
    cpa16(st_ + PLB + d0, sAl0 + k_);      cpa16(st_ + PLB + d1, sAl1 + k_); \
    cpa16(st_ + 2 * PLB + d0, sBh0 + k_);  cpa16(st_ + 2 * PLB + d1, sBh1 + k_); \
    cpa16(st_ + 3 * PLB + d0, sBl0 + k_);  cpa16(st_ + 3 * PLB + d1, sBl1 + k_); } while (0)

    float acc[4][4][4];
#pragma unroll
    for (int a = 0; a < 4; a++)
#pragma unroll
        for (int b = 0; b < 4; b++)
#pragma unroll
            for (int c = 0; c < 4; c++) acc[a][b][c] = 0.f;

    int nk = K / 32;
    LOAD_STAGE(0, 0);  CPA_COMMIT();
    LOAD_STAGE(1, 32); CPA_COMMIT();

    for (int it = 0; it < nk; it++) {
        CPA_WAIT1();
        __syncthreads();
        u32 stg = smb + (it % NSTG) * STG_B;
        compute_k16(stg, 0, wm, wn, lane, acc);
        compute_k16(stg, 1, wm, wn, lane, acc);
        if (it + 2 < nk) LOAD_STAGE((it + 2) % NSTG, (it + 2) * 32);
        CPA_COMMIT();
    }
    CPA_WAIT0();
    __syncthreads();

    if constexpr (MODE == M_SCORES) {
#pragma unroll
        for (int mf = 0; mf < 4; mf++) {
#pragma unroll
            for (int half = 0; half < 2; half++) {
                int r = wm * 64 + mf * 16 + g + half * 8;
                float rs = 0.f;
#pragma unroll
                for (int nf = 0; nf < 4; nf++) {
                    int cn = wn * 32 + nf * 8 + tig * 2;
                    float e0 = __expf(acc[mf][nf][half * 2 + 0] * INV_SQRT_DH + s_row[cn]);
                    float e1 = __expf(acc[mf][nf][half * 2 + 1] * INV_SQRT_DH + s_row[cn + 1]);
                    rs += e0 + e1;
                    u32 h, l;
                    split2(e0, e1, h, l);
                    size_t ix = (coff + (size_t)r * S_ + cn) >> 1;
                    g_Ps_h[ix] = h;
                    g_Ps_l[ix] = l;
                }
                rs += __shfl_xor_sync(0xffffffffu, rs, 1);
                rs += __shfl_xor_sync(0xffffffffu, rs, 2);
                if (tig == 0) atomicAdd(&g_L[(size_t)z * S_ + m0 + r], rs);
            }
        }
    } else if constexpr (MODE == M_CTX) {
#pragma unroll
        for (int mf = 0; mf < 4; mf++) {
#pragma unroll
            for (int half = 0; half < 2; half++) {
                int m = wm * 64 + mf * 16 + g + half * 8;
                float iv = s_row[m];
#pragma unroll
                for (int nf = 0; nf < 4; nf++) {
                    int n = wn * 32 + nf * 8 + tig * 2;
                    u32 h, l;
                    split2(acc[mf][nf][half * 2 + 0] * iv, acc[mf][nf][half * 2 + 1] * iv, h, l);
                    size_t ix = (coff + (size_t)m * ldc + n) >> 1;
                    Ch[ix] = h;
                    Cl[ix] = l;
                }
            }
        }
    } else {  // M_XA: fp32 out
        float* C = Cf + coff;
#pragma unroll
        for (int mf = 0; mf < 4; mf++) {
#pragma unroll
            for (int half = 0; half < 2; half++) {
                int m = wm * 64 + mf * 16 + g + half * 8;
#pragma unroll
                for (int nf = 0; nf < 4; nf++) {
                    int n = wn * 32 + nf * 8 + tig * 2;
                    float2 v = {acc[mf][nf][half * 2 + 0], acc[mf][nf][half * 2 + 1]};
                    *(float2*)(C + (size_t)m * ldc + n) = v;
                }
            }
        }
    }
#undef LOAD_STAGE
}

// ======== wide (128x256): QKV / MOE ========
template <int MODE>
__global__ void __launch_bounds__(256) tc_gemm_w(
    cbf* Ah_, cbf* Al_, cbf* Bh_, cbf* Bl_,
    float* __restrict__ Cf,
    const float* __restrict__ Lbb,
    const int* __restrict__ glist, const int* __restrict__ gcnt,
    const float* __restrict__ gw,
    const float* __restrict__ Lb2, const float* __restrict__ Lb3) {
    constexpr bool QKV = (MODE == M_QKV);
    extern __shared__ __align__(16) unsigned char dsm[];
    __shared__ int esm[128];
    __shared__ int tok[128];

    int tid = threadIdx.x;
    int m0 = blockIdx.y * 128, n0 = blockIdx.x * 256, z = blockIdx.z;

    cbf *pAh, *pAl, *pBh, *pBl;
    const float* La;
    const float* Lb;

    if constexpr (MODE == M_QKV) {
        pAh = (cbf*)g_xs_h; pAl = (cbf*)g_xs_l;
        size_t bo = (size_t)n0 * H_;
        if (z == 0)      { pBh = (cbf*)g_wqs_h + bo; pBl = (cbf*)g_wqs_l + bo; }
        else if (z == 1) { pBh = (cbf*)g_wks_h + bo; pBl = (cbf*)g_wks_l + bo; }
        else {
            size_t eo = (size_t)(z - 2) * H_ * H_;
            pBh = (cbf*)g_vbs_h + eo + bo; pBl = (cbf*)g_vbs_l + eo + bo;
        }
        La = g_xacat + (z == 0 ? 0 : (z == 1 ? 16 : 32 + (z - 2) * R_));
        Lb = (z == 0 ? Lbb : (z == 1 ? Lb2 : Lb3 + (size_t)(z - 2) * H_ * R_)) + (size_t)n0 * R_;
    } else {  // M_MOE
        pAh = Ah_; pAl = Al_;
        pBh = Bh_ + (size_t)z * H_ * H_ + (size_t)n0 * H_;
        pBl = Bl_ + (size_t)z * H_ * H_ + (size_t)n0 * H_;
        La = g_xao + z * R_;
        Lb = Lbb + (size_t)z * H_ * R_ + (size_t)n0 * R_;
    }

    if constexpr (QKV) {
        if (z >= 2 && m0 >= gcnt[z - 2]) return;
        if (tid < 128) {
            if (z < 2) { tok[tid] = m0 + tid; esm[tid] = 0; }
            else {
                int count = gcnt[z - 2];
                int idx = m0 + tid;
                int en = (idx < count) ? glist[(z - 2) * T_ + idx] : -1;
                esm[tid] = en;
                tok[tid] = (en >= 0) ? (en >> 1) : 0;
            }
        }
        __syncthreads();
    } else {
        int count = gcnt[z];
        if (m0 >= count) return;
        if (tid < 128) {
            int idx = m0 + tid;
            int en = (idx < count) ? glist[z * T_ + idx] : -1;
            esm[tid] = en;
            tok[tid] = (en >= 0) ? (en >> 1) : 0;
        }
        __syncthreads();
    }

    int wid = tid >> 5, lane = tid & 31;
    int wm = wid & 1, wn = wid >> 1, g = lane >> 2, tig = lane & 3;
    u32 smb = s2u(dsm);

    int cr = tid >> 2, seg = tid & 3;
    long ga0 = (long)tok[cr];
    long ga1 = (long)tok[cr + 64];
    cbf* sAh0 = pAh + ga0 * H_ + seg * 8;
    cbf* sAh1 = pAh + ga1 * H_ + seg * 8;
    cbf* sAl0 = pAl + ga0 * H_ + seg * 8;
    cbf* sAl1 = pAl + ga1 * H_ + seg * 8;
    u32 dA0 = swb(cr, seg), dA1 = swb(cr + 64, seg);
    cbf* sBh[4]; cbf* sBl[4]; u32 dB[4];
#pragma unroll
    for (int c = 0; c < 4; c++) {
        int row = cr + 64 * c;
        sBh[c] = pBh + (long)row * H_ + seg * 8;
        sBl[c] = pBl + (long)row * H_ + seg * 8;
        dB[c] = swb(row, seg);
    }

#define LOAD_STAGE_W(s, ktE) do { u32 st_ = smb + (s) * STG2; int k_ = (ktE); \
    cpa16(st_ + dA0, sAh0 + k_);       cpa16(st_ + dA1, sAh1 + k_); \
    cpa16(st_ + PLB + dA0, sAl0 + k_); cpa16(st_ + PLB + dA1, sAl1 + k_); \
    u32 bb_ = st_ + 2 * PLB; \
    cpa16(bb_ + dB[0], sBh[0] + k_); cpa16(bb_ + dB[1], sBh[1] + k_); \
    cpa16(bb_ + dB[2], sBh[2] + k_); cpa16(bb_ + dB[3], sBh[3] + k_); \
    u32 bl_ = bb_ + PLB2; \
    cpa16(bl_ + dB[0], sBl[0] + k_); cpa16(bl_ + dB[1], sBl[1] + k_); \
    cpa16(bl_ + dB[2], sBl[2] + k_); cpa16(bl_ + dB[3], sBl[3] + k_); } while (0)

    float acc[4][8][4];
#pragma unroll
    for (int a = 0; a < 4; a++)
#pragma unroll
        for (int b = 0; b < 8; b++)
#pragma unroll
            for (int c = 0; c < 4; c++) acc[a][b][c] = 0.f;

    int nk = H_ / 32;
    LOAD_STAGE_W(0, 0);  CPA_COMMIT();
    LOAD_STAGE_W(1, 32); CPA_COMMIT();

    for (int it = 0; it < nk; it++) {
        CPA_WAIT1();
        __syncthreads();
        u32 stg = smb + (it % NSTG) * STG2;
        compute_k16_w(stg, 0, wm, wn, lane, acc);
        compute_k16_w(stg, 1, wm, wn, lane, acc);
        if (it + 2 < nk) LOAD_STAGE_W((it + 2) % NSTG, (it + 2) * 32);
        CPA_COMMIT();
    }
    CPA_WAIT0();
    __syncthreads();

    // LoRA extra k16: A = SCALING*La (rows via tok), B = Lb (256 rows x 16)
#pragma unroll
    for (int i = 0; i < 2; i++) {
        int f = tid + i * 256;
        int row = f >> 2, kc = (f & 3) * 4;
        size_t ro = (size_t)tok[row] * 128;
        float4 v = *(const float4*)(La + ro + kc);
        v.x *= SCALING_; v.y *= SCALING_; v.z *= SCALING_; v.w *= SCALING_;
        u32 h0, h1, l0, l1;
        split4(v, h0, h1, l0, l1);
        u32 off = smb + swb(row, kc >> 3) + (kc & 7) * 2;
        asm volatile("st.shared.v2.u32 [%0], {%1,%2};" :: "r"(off), "r"(h0), "r"(h1));
        asm volatile("st.shared.v2.u32 [%0], {%1,%2};" :: "r"(off + PLB), "r"(l0), "r"(l1));
    }
#pragma unroll
    for (int i = 0; i < 4; i++) {
        int f = tid + i * 256;
        int row = f >> 2, kc = (f & 3) * 4;
        float4 u = *(const float4*)(Lb + (size_t)row * R_ + kc);
        u32 h0, h1, l0, l1;
        split4(u, h0, h1, l0, l1);
        u32 off = smb + 2 * PLB + swb(row, kc >> 3) + (kc & 7) * 2;
        asm volatile("st.shared.v2.u32 [%0], {%1,%2};" :: "r"(off), "r"(h0), "r"(h1));
        asm volatile("st.shared.v2.u32 [%0], {%1,%2};" :: "r"(off + PLB2), "r"(l0), "r"(l1));
    }
    __syncthreads();
    compute_k16_w(smb, 0, wm, wn, lane, acc);

    // ---------------- epilogues ----------------
    if constexpr (QKV) {
        if (z < 2) {
            u32* ch = (z == 0) ? g_qs_h : g_ks_h;
            u32* cl = (z == 0) ? g_qs_l : g_ks_l;
            size_t co = (size_t)m0 * H_ + n0;
#pragma unroll
            for (int mf = 0; mf < 4; mf++) {
#pragma unroll
                for (int half = 0; half < 2; half++) {
                    int m = wm * 64 + mf * 16 + g + half * 8;
#pragma unroll
                    for (int nf = 0; nf < 8; nf++) {
                        int n = wn * 64 + nf * 8 + tig * 2;
                        u32 h, l;
                        split2(acc[mf][nf][half * 2 + 0], acc[mf][nf][half * 2 + 1], h, l);
                        size_t ix = (co + (size_t)m * H_ + n) >> 1;
                        ch[ix] = h;
                        cl[ix] = l;
                    }
                }
            }
        } else {
            // V MoE: untransposed coalesced atomic accumulate into g_vt[t][n]
#pragma unroll
            for (int mf = 0; mf < 4; mf++) {
#pragma unroll
                for (int half = 0; half < 2; half++) {
                    int lr = wm * 64 + mf * 16 + g + half * 8;
                    int en = esm[lr];
                    if (en < 0) continue;
                    float w = gw[en];
                    int t = en >> 1;
                    float* p = g_vt + (size_t)t * H_ + n0;
#pragma unroll
                    for (int nf = 0; nf < 8; nf++) {
                        int n = wn * 64 + nf * 8 + tig * 2;
                        atomicAdd(p + n, w * acc[mf][nf][half * 2 + 0]);
                        atomicAdd(p + n + 1, w * acc[mf][nf][half * 2 + 1]);
                    }
                }
            }
        }
    } else {  // M_MOE -> out
#pragma unroll
        for (int mf = 0; mf < 4; mf++) {
#pragma unroll
            for (int half = 0; half < 2; half++) {
                int lr = wm * 64 + mf * 16 + g + half * 8;
                int en = esm[lr];
                if (en < 0) continue;
                float w = gw[en];
                int t = en >> 1;
                float* p = Cf + (size_t)t * H_ + n0;
#pragma unroll
                for (int nf = 0; nf < 8; nf++) {
                    int n = wn * 64 + nf * 8 + tig * 2;
                    atomicAdd(p + n, w * acc[mf][nf][half * 2 + 0]);
                    atomicAdd(p + n + 1, w * acc[mf][nf][half * 2 + 1]);
                }
            }
        }
    }
#undef LOAD_STAGE_W
}

// ---------------- transpose + split: g_vt [b][s][n] -> vts planes [b*H+n][S] ----------------
__global__ void tsplit_kernel() {
    __shared__ float tile[32][33];
    int bx = blockIdx.x, by = blockIdx.y, bz = blockIdx.z;
    int tx = threadIdx.x & 31, ty = threadIdx.x >> 5;
#pragma unroll
    for (int r = 0; r < 32; r += 8) {
        tile[r + ty][tx] = g_vt[((size_t)(bz * S_ + by * 32 + r + ty)) * H_ + bx * 32 + tx];
    }
    __syncthreads();
#pragma unroll
    for (int r = 0; r < 32; r += 8) {
        int n = r + ty;
        if (tx < 16) {
            float a = tile[2 * tx][n], b = tile[2 * tx + 1][n];
            u32 h, l;
            split2(a, b, h, l);
            size_t ix = (((size_t)(bz * H_ + bx * 32 + n)) * S_ + by * 32) / 2 + tx;
            g_vts_h[ix] = h;
            g_vts_l[ix] = l;
        }
    }
}

// ---------------- split fp32 -> bf16 hi/lo planes ----------------
__global__ void split_kernel(const float4* __restrict__ src, u32* __restrict__ hi,
                             u32* __restrict__ lo, int n4) {
    for (int i = blockIdx.x * blockDim.x + threadIdx.x; i < n4; i += gridDim.x * blockDim.x) {
        float4 v = src[i];
        u32 h0, h1, l0, l1;
        split4(v, h0, h1, l0, l1);
        *(uint2*)&hi[(size_t)i * 2] = make_uint2(h0, h1);
        *(uint2*)&lo[(size_t)i * 2] = make_uint2(l0, l1);
    }
}

// ---------------- init counts ----------------
__global__ void init_counts_kernel() {
    if (threadIdx.x < E_) {
        g_cnt_v[threadIdx.x] = 0;
        g_cnt_o[threadIdx.x] = 0;
    }
}

// ---------------- routing ----------------
__global__ void routing_kernel(const float* __restrict__ x,
                               const float* __restrict__ gv,
                               const float* __restrict__ go) {
    int t = blockIdx.x;
    const float* xt = x + (size_t)t * H_;
    float pv[E_], po[E_];
#pragma unroll
    for (int e = 0; e < E_; e++) { pv[e] = 0.f; po[e] = 0.f; }
    for (int k = threadIdx.x; k < H_; k += 128) {
        float xv = xt[k];
#pragma unroll
        for (int e = 0; e < E_; e++) {
            pv[e] += xv * gv[e * H_ + k];
            po[e] += xv * go[e * H_ + k];
        }
    }
    __shared__ float red[2 * E_][128];
#pragma unroll
    for (int e = 0; e < E_; e++) {
        red[e][threadIdx.x] = pv[e];
        red[E_ + e][threadIdx.x] = po[e];
    }
    __syncthreads();
    if (threadIdx.x < 2 * E_) {
        float s = 0.f;
        for (int i = 0; i < 128; i++) s += red[threadIdx.x][i];
        red[threadIdx.x][0] = s;
    }
    __syncthreads();
    if (threadIdx.x < 2) {
        bool isO = (threadIdx.x == 1);
        float sc[E_];
#pragma unroll
        for (int e = 0; e < E_; e++) {
            float d = red[(isO ? E_ : 0) + e][0];
            sc[e] = 1.f / (1.f + expf(-d));
        }
        int e0 = 0;
        for (int e = 1; e < E_; e++) if (sc[e] > sc[e0]) e0 = e;
        int e1 = -1;
        for (int e = 0; e < E_; e++) {
            if (e == e0) continue;
            if (e1 < 0 || sc[e] > sc[e1]) e1 = e;
        }
        float t1 = expf(sc[e1] - sc[e0]);
        float w0 = 1.f / (1.f + t1);
        float w1 = t1 / (1.f + t1);
        if (!isO) {
            g_wslot_v[t * 2 + 0] = w0;
            g_wslot_v[t * 2 + 1] = w1;
            int p0 = atomicAdd(&g_cnt_v[e0], 1); g_list_v[e0 * T_ + p0] = t * 2 + 0;
            int p1 = atomicAdd(&g_cnt_v[e1], 1); g_list_v[e1 * T_ + p1] = t * 2 + 1;
        } else {
            g_wslot_o[t * 2 + 0] = w0;
            g_wslot_o[t * 2 + 1] = w1;
            int p0 = atomicAdd(&g_cnt_o[e0], 1); g_list_o[e0 * T_ + p0] = t * 2 + 0;
            int p1 = atomicAdd(&g_cnt_o[e1], 1); g_list_o[e1 * T_ + p1] = t * 2 + 1;
        }
    }
}

// ---------------- launcher ----------------
extern "C" void kernel_launch(void* const* d_in, const int* in_sizes, int n_in,
                              void* d_out, int out_size) {
    const float* x      = (const float*)d_in[0];
    const float* amask  = (const float*)d_in[1];
    const float* wq     = (const float*)d_in[2];
    const float* wk     = (const float*)d_in[3];
    const float* q_a    = (const float*)d_in[4];
    const float* q_b    = (const float*)d_in[5];
    const float* k_a    = (const float*)d_in[6];
    const float* k_b    = (const float*)d_in[7];
    const float* gv     = (const float*)d_in[8];
    const float* go     = (const float*)d_in[9];
    const float* v_base = (const float*)d_in[10];
    const float* v_a    = (const float*)d_in[11];
    const float* v_b    = (const float*)d_in[12];
    const float* o_base = (const float*)d_in[13];
    const float* o_a    = (const float*)d_in[14];
    const float* o_b    = (const float*)d_in[15];
    float* out = (float*)d_out;

#define SYM(v, s) void* v; cudaGetSymbolAddress(&v, s)
    SYM(p_vt, g_vt); SYM(p_L, g_L); SYM(p_xacat, g_xacat); SYM(p_xao, g_xao);
    SYM(p_wcat, g_wcat); SYM(p_wcat2, g_wcat2);
    SYM(p_list_v, g_list_v); SYM(p_list_o, g_list_o);
    SYM(p_cnt_v, g_cnt_v); SYM(p_cnt_o, g_cnt_o);
    SYM(p_ws_v, g_wslot_v); SYM(p_ws_o, g_wslot_o);
    SYM(xs_h, g_xs_h); SYM(xs_l, g_xs_l);
    SYM(qs_h, g_qs_h); SYM(qs_l, g_qs_l);
    SYM(ks_h, g_ks_h); SYM(ks_l, g_ks_l);
    SYM(cts_h, g_cts_h); SYM(cts_l, g_cts_l);
    SYM(vts_h, g_vts_h); SYM(vts_l, g_vts_l);
    SYM(Ps_h, g_Ps_h); SYM(Ps_l, g_Ps_l);
    SYM(wqs_h, g_wqs_h); SYM(wqs_l, g_wqs_l);
    SYM(wks_h, g_wks_h); SYM(wks_l, g_wks_l);
    SYM(vbs_h, g_vbs_h); SYM(vbs_l, g_vbs_l);
    SYM(obs_h, g_obs_h); SYM(obs_l, g_obs_l);
    SYM(wcs_h, g_wcs_h); SYM(wcs_l, g_wcs_l);
    SYM(wcs2_h, g_wcs2_h); SYM(wcs2_l, g_wcs2_l);
#undef SYM

    cudaFuncSetAttribute(tc_gemm<M_XA>,     cudaFuncAttributeMaxDynamicSharedMemorySize, SMEM_SZ);
    cudaFuncSetAttribute(tc_gemm<M_SCORES>, cudaFuncAttributeMaxDynamicSharedMemorySize, SMEM_SZ);
    cudaFuncSetAttribute(tc_gemm<M_CTX>,    cudaFuncAttributeMaxDynamicSharedMemorySize, SMEM_SZ);
    cudaFuncSetAttribute(tc_gemm_w<M_QKV>,  cudaFuncAttributeMaxDynamicSharedMemorySize, SMEM2);
    cudaFuncSetAttribute(tc_gemm_w<M_MOE>,  cudaFuncAttributeMaxDynamicSharedMemorySize, SMEM2);

    // LoRA-A weight concats (fp32)
    cudaMemcpyAsync((float*)p_wcat,           q_a, sizeof(float) * R_ * H_,      cudaMemcpyDeviceToDevice);
    cudaMemcpyAsync((float*)p_wcat + 16 * H_, k_a, sizeof(float) * R_ * H_,      cudaMemcpyDeviceToDevice);
    cudaMemcpyAsync((float*)p_wcat + 32 * H_, v_a, sizeof(float) * E_ * R_ * H_, cudaMemcpyDeviceToDevice);
    cudaMemcpyAsync((float*)p_wcat2,          o_a, sizeof(float) * E_ * R_ * H_, cudaMemcpyDeviceToDevice);

    cudaMemsetAsync(p_vt, 0, sizeof(float) * (size_t)T_ * H_);
    cudaMemsetAsync(p_L, 0, sizeof(float) * (size_t)B_ * NH_ * S_);
    cudaMemsetAsync(out, 0, sizeof(float) * (size_t)T_ * H_);
    init_counts_kernel<<<1, 32>>>();
    routing_kernel<<<T_, 128>>>(x, gv, go);

    // splits: inputs + weights
    split_kernel<<<1024, 256>>>((const float4*)x,      (u32*)xs_h,  (u32*)xs_l,  T_ * H_ / 4);
    split_kernel<<<1024, 256>>>((const float4*)wq,     (u32*)wqs_h, (u32*)wqs_l, H_ * H_ / 4);
    split_kernel<<<1024, 256>>>((const float4*)wk,     (u32*)wks_h, (u32*)wks_l, H_ * H_ / 4);
    split_kernel<<<2048, 256>>>((const float4*)v_base, (u32*)vbs_h, (u32*)vbs_l, E_ * H_ * H_ / 4);
    split_kernel<<<2048, 256>>>((const float4*)o_base, (u32*)obs_h, (u32*)obs_l, E_ * H_ * H_ / 4);
    split_kernel<<<256, 256>>>((const float4*)p_wcat,  (u32*)wcs_h, (u32*)wcs_l, 128 * H_ / 4);
    split_kernel<<<256, 256>>>((const float4*)p_wcat2, (u32*)wcs2_h, (u32*)wcs2_l, 128 * H_ / 4);

    // XA: xacat = x @ wcat^T (fp32 out)
    tc_gemm<M_XA><<<dim3(1, T_ / 128), 256, SMEM_SZ>>>(
        (cbf*)xs_h, (cbf*)xs_l, (cbf*)wcs_h, (cbf*)wcs_l,
        (float*)p_xacat, nullptr, nullptr, nullptr);

    // fused Q-proj (z=0), K-proj (z=1), V-MoE (z=2..7): wide 128x256 tiles
    tc_gemm_w<M_QKV><<<dim3(H_ / 256, T_ / 128, 2 + E_), 256, SMEM2>>>(
        nullptr, nullptr, nullptr, nullptr,
        nullptr, q_b,
        (const int*)p_list_v, (const int*)p_cnt_v, (const float*)p_ws_v,
        k_b, v_b);

    // transpose + split V -> vts planes
    tsplit_kernel<<<dim3(H_ / 32, S_ / 32, B_), 256>>>();

    // attention: scores with fused exp + row-sum epilogue, then ctx with 1/L epilogue
    tc_gemm<M_SCORES><<<dim3(S_ / 128, S_ / 128, B_ * NH_), 256, SMEM_SZ>>>(
        (cbf*)qs_h, (cbf*)qs_l, (cbf*)ks_h, (cbf*)ks_l,
        nullptr, nullptr, nullptr, amask);
    tc_gemm<M_CTX><<<dim3(1, S_ / 128, B_ * NH_), 256, SMEM_SZ>>>(
        (cbf*)Ps_h, (cbf*)Ps_l, (cbf*)vts_h, (cbf*)vts_l,
        nullptr, (u32*)cts_h, (u32*)cts_l, nullptr);

    // O path
    tc_gemm<M_XA><<<dim3(1, T_ / 128), 256, SMEM_SZ>>>(
        (cbf*)cts_h, (cbf*)cts_l, (cbf*)wcs2_h, (cbf*)wcs2_l,
        (float*)p_xao, nullptr, nullptr, nullptr);
    tc_gemm_w<M_MOE><<<dim3(H_ / 256, T_ / 128, E_), 256, SMEM2>>>(
        (cbf*)cts_h, (cbf*)cts_l, (cbf*)obs_h, (cbf*)obs_l,
        out, o_b,
        (const int*)p_list_o, (const int*)p_cnt_o, (const float*)p_ws_o,
        nullptr, nullptr);
}

// round 15
// speedup vs baseline: 1.0276x; 1.0276x over previous
#include <cuda_runtime.h>
#include <cuda_bf16.h>
#include <math.h>

typedef unsigned int u32;
typedef unsigned long long u64;

// ---------------- problem constants ----------------
#define B_   2
#define S_   2048
#define H_   2048
#define NH_  16
#define DH_  128
#define E_   6
#define R_   16
#define T_   (B_ * S_)            // 4096 tokens
#define SCALING_ 8.0f
#define INV_SQRT_DH 0.08838834764831845f

// tile: 128 rows x 32 bf16 = 64B/row, XOR-swizzled. 8KB per plane.
#define PLB 8192
#define STG_B (4 * PLB)           // Ahi, Alo, Bhi, Blo = 32KB
#define NSTG 3
#define SMEM_SZ (NSTG * STG_B)    // 96KB

// ---------------- scratch: fp32 ----------------
__device__ float g_vt[T_ * H_];        // V untransposed [t][n] (atomic accum)
__device__ float g_L[B_ * NH_ * S_];   // unnormalized softmax row sums
__device__ float g_xacat[T_ * 128];
__device__ float g_xao[T_ * 128];
__device__ float g_wcat[128 * H_];
__device__ float g_wcat2[128 * H_];
__device__ int   g_list_v[E_ * T_];
__device__ int   g_list_o[E_ * T_];
__device__ int   g_cnt_v[E_];
__device__ int   g_cnt_o[E_];
__device__ float g_wslot_v[T_ * 2];
__device__ float g_wslot_o[T_ * 2];

// ---------------- scratch: bf16 hi/lo planes (u32 = 2 bf16) ----------------
#define PT (T_ * H_ / 2)
#define PW (H_ * H_ / 2)
#define PE (E_ * H_ * H_ / 2)
#define PC (128 * H_ / 2)
__device__ u32 g_xs_h[PT],  g_xs_l[PT];
__device__ u32 g_qs_h[PT],  g_qs_l[PT];
__device__ u32 g_ks_h[PT],  g_ks_l[PT];
__device__ u32 g_cts_h[PT], g_cts_l[PT];
__device__ u32 g_vts_h[PT], g_vts_l[PT];   // V transposed planes [b*H+n][S]
__device__ u32 g_Ps_h[(size_t)B_ * NH_ * S_ * S_ / 2];
__device__ u32 g_Ps_l[(size_t)B_ * NH_ * S_ * S_ / 2];
__device__ u32 g_wqs_h[PW], g_wqs_l[PW];
__device__ u32 g_wks_h[PW], g_wks_l[PW];
__device__ u32 g_vbs_h[PE], g_vbs_l[PE];
__device__ u32 g_obs_h[PE], g_obs_l[PE];
__device__ u32 g_wcs_h[PC], g_wcs_l[PC];
__device__ u32 g_wcs2_h[PC], g_wcs2_l[PC];

// ---------------- helpers ----------------
__device__ __forceinline__ u32 s2u(const void* p) {
    u32 a;
    asm("{ .reg .u64 t; cvta.to.shared.u64 t, %1; cvt.u32.u64 %0, t; }" : "=r"(a) : "l"(p));
    return a;
}
__device__ __forceinline__ u32 pack_bf2(float a, float b) {
    __nv_bfloat162 t = __floats2bfloat162_rn(a, b);
    return *reinterpret_cast<u32*>(&t);
}
__device__ __forceinline__ void split4(float4 v, u32& h0, u32& h1, u32& l0, u32& l1) {
    __nv_bfloat162 p0 = __floats2bfloat162_rn(v.x, v.y);
    __nv_bfloat162 p1 = __floats2bfloat162_rn(v.z, v.w);
    h0 = *reinterpret_cast<u32*>(&p0);
    h1 = *reinterpret_cast<u32*>(&p1);
    l0 = pack_bf2(v.x - __low2float(p0), v.y - __high2float(p0));
    l1 = pack_bf2(v.z - __low2float(p1), v.w - __high2float(p1));
}
__device__ __forceinline__ void split2(float a, float b, u32& h, u32& l) {
    __nv_bfloat162 p = __floats2bfloat162_rn(a, b);
    h = *reinterpret_cast<u32*>(&p);
    l = pack_bf2(a - __low2float(p), b - __high2float(p));
}
__device__ __forceinline__ void mma_bf16(float* c, u32 a0, u32 a1, u32 a2, u32 a3, u32 b0, u32 b1) {
    asm volatile(
        "mma.sync.aligned.m16n8k16.row.col.f32.bf16.bf16.f32 "
        "{%0,%1,%2,%3}, {%4,%5,%6,%7}, {%8,%9}, {%0,%1,%2,%3};"
        : "+f"(c[0]), "+f"(c[1]), "+f"(c[2]), "+f"(c[3])
        : "r"(a0), "r"(a1), "r"(a2), "r"(a3), "r"(b0), "r"(b1));
}
__device__ __forceinline__ void ldsm4(u32* r, u32 a) {
    asm volatile("ldmatrix.sync.aligned.m8n8.x4.shared.b16 {%0,%1,%2,%3}, [%4];"
        : "=r"(r[0]), "=r"(r[1]), "=r"(r[2]), "=r"(r[3]) : "r"(a));
}
__device__ __forceinline__ void cpa16(u32 dst, const void* src) {
    asm volatile("cp.async.ca.shared.global [%0], [%1], 16;" :: "r"(dst), "l"(src));
}
#define CPA_COMMIT() asm volatile("cp.async.commit_group;" ::: "memory")
#define CPA_WAIT1()  asm volatile("cp.async.wait_group 1;" ::: "memory")
#define CPA_WAIT0()  asm volatile("cp.async.wait_group 0;" ::: "memory")
// XOR swizzle: row 64B, seg = 16B chunk idx (0..3)
__device__ __forceinline__ u32 swb(int row, int seg) {
    return (u32)(row * 64 + ((seg ^ ((row >> 1) & 3)) * 16));
}

// one k16 MMA step over 128x128 tile (3-term bf16 split), stage base = stg
__device__ __forceinline__ void compute_k16(u32 stg, int ks, int wm, int wn, int lane,
                                            float (&acc)[4][4][4]) {
    int j = lane >> 3, r7 = lane & 7;
    int rowA = wm * 64 + (j & 1) * 8 + r7;
    int segA = ks * 2 + (j >> 1);
    u32 aH = stg + swb(rowA, segA);
    u32 aL = aH + PLB;
    int rowB = wn * 32 + (j >> 1) * 8 + r7;
    int segB = ks * 2 + (j & 1);
    u32 bH = stg + 2 * PLB + swb(rowB, segB);
    u32 bL = bH + PLB;

    u32 bh[2][4], bl[2][4], am[4][4];
    ldsm4(bh[0], bH); ldsm4(bh[1], bH + 1024);
    ldsm4(bl[0], bL); ldsm4(bl[1], bL + 1024);
#pragma unroll
    for (int mf = 0; mf < 4; mf++) ldsm4(am[mf], aH + mf * 1024);
#pragma unroll
    for (int mf = 0; mf < 4; mf++)
#pragma unroll
        for (int nf = 0; nf < 4; nf++) {
            const u32* b = &bh[nf >> 1][(nf & 1) * 2];
            mma_bf16(acc[mf][nf], am[mf][0], am[mf][1], am[mf][2], am[mf][3], b[0], b[1]);
        }
#pragma unroll
    for (int mf = 0; mf < 4; mf++)
#pragma unroll
        for (int nf = 0; nf < 4; nf++) {
            const u32* b = &bl[nf >> 1][(nf & 1) * 2];
            mma_bf16(acc[mf][nf], am[mf][0], am[mf][1], am[mf][2], am[mf][3], b[0], b[1]);
        }
#pragma unroll
    for (int mf = 0; mf < 4; mf++) ldsm4(am[mf], aL + mf * 1024);
#pragma unroll
    for (int mf = 0; mf < 4; mf++)
#pragma unroll
        for (int nf = 0; nf < 4; nf++) {
            const u32* b = &bh[nf >> 1][(nf & 1) * 2];
            mma_bf16(acc[mf][nf], am[mf][0], am[mf][1], am[mf][2], am[mf][3], b[0], b[1]);
        }
}

// ---------------- the one NT GEMM kernel ----------------
enum { M_XA = 1, M_MOE = 2, M_SCORES = 4, M_CTX = 5, M_QKV = 6 };

typedef const __nv_bfloat16 cbf;

template <int MODE>
__global__ void __launch_bounds__(256) tc_gemm(
    cbf* Ah_, cbf* Al_, cbf* Bh_, cbf* Bl_,
    float* __restrict__ Cf, u32* __restrict__ Ch, u32* __restrict__ Cl,
    const float* __restrict__ Lab, const float* __restrict__ Lbb,
    const int* __restrict__ glist, const int* __restrict__ gcnt,
    const float* __restrict__ gw,
    const float* __restrict__ Lb2, const float* __restrict__ Lb3) {
    constexpr bool GATHER = (MODE == M_MOE);
    constexpr bool QKV = (MODE == M_QKV);
    constexpr bool LORA = (MODE == M_MOE || MODE == M_QKV);
    constexpr bool USETOK = (GATHER || QKV);
    extern __shared__ __align__(16) unsigned char dsm[];
    __shared__ int esm[128];
    __shared__ int tok[128];
    __shared__ float s_row[128];

    int tid = threadIdx.x;
    int m0 = blockIdx.y * 128, n0 = blockIdx.x * 128, z = blockIdx.z;

    cbf *pAh, *pAl, *pBh, *pBl;
    const float* La = nullptr;
    const float* Lb = nullptr;
    long lda, ldb, ldc = 0;
    int K, ldla = 0;
    size_t coff = 0;

    if constexpr (MODE == M_XA) {
        pAh = Ah_ + (size_t)m0 * H_; pAl = Al_ + (size_t)m0 * H_;
        pBh = Bh_; pBl = Bl_;
        coff = (size_t)m0 * 128;
        lda = ldb = H_; ldc = 128; K = H_;
    } else if constexpr (MODE == M_MOE) {
        pAh = Ah_; pAl = Al_;
        pBh = Bh_ + (size_t)z * H_ * H_ + (size_t)n0 * H_;
        pBl = Bl_ + (size_t)z * H_ * H_ + (size_t)n0 * H_;
        lda = ldb = H_; K = H_;
        La = Lab + z * R_; ldla = 128;
        Lb = Lbb + (size_t)z * H_ * R_ + (size_t)n0 * R_;
    } else if constexpr (MODE == M_QKV) {
        pAh = (cbf*)g_xs_h; pAl = (cbf*)g_xs_l;
        size_t bo = (size_t)n0 * H_;
        if (z == 0)      { pBh = (cbf*)g_wqs_h + bo; pBl = (cbf*)g_wqs_l + bo; }
        else if (z == 1) { pBh = (cbf*)g_wks_h + bo; pBl = (cbf*)g_wks_l + bo; }
        else {
            size_t eo = (size_t)(z - 2) * H_ * H_;
            pBh = (cbf*)g_vbs_h + eo + bo; pBl = (cbf*)g_vbs_l + eo + bo;
        }
        lda = ldb = H_; K = H_; ldla = 128;
        La = g_xacat + (z == 0 ? 0 : (z == 1 ? 16 : 32 + (z - 2) * R_));
        Lb = (z == 0 ? Lbb : (z == 1 ? Lb2 : Lb3 + (size_t)(z - 2) * H_ * R_)) + (size_t)n0 * R_;
    } else if constexpr (MODE == M_SCORES) {
        int b = z >> 4, h = z & 15;
        size_t ao = ((size_t)b * S_ + m0) * H_ + h * DH_;
        size_t bo = ((size_t)b * S_ + n0) * H_ + h * DH_;
        pAh = Ah_ + ao; pAl = Al_ + ao;
        pBh = Bh_ + bo; pBl = Bl_ + bo;
        coff = (size_t)z * S_ * S_ + (size_t)m0 * S_ + n0;
        lda = ldb = H_; ldc = S_; K = DH_;
    } else {  // M_CTX
        size_t ao = (size_t)z * S_ * S_ + (size_t)m0 * S_;
        size_t bo = (size_t)z * DH_ * S_;
        pAh = Ah_ + ao; pAl = Al_ + ao;
        pBh = Bh_ + bo; pBl = Bl_ + bo;
        int b = z >> 4, h = z & 15;
        coff = ((size_t)b * S_ + m0) * H_ + h * DH_;
        lda = S_; ldb = S_; ldc = H_; K = S_;
    }

    if constexpr (MODE == M_QKV) {
        if (z >= 2 && m0 >= gcnt[z - 2]) return;
        if (tid < 128) {
            if (z < 2) { tok[tid] = m0 + tid; esm[tid] = 0; }
            else {
                int count = gcnt[z - 2];
                int idx = m0 + tid;
                int en = (idx < count) ? glist[(z - 2) * T_ + idx] : -1;
                esm[tid] = en;
                tok[tid] = (en >= 0) ? (en >> 1) : 0;
            }
        }
        __syncthreads();
    } else if constexpr (GATHER) {
        int count = gcnt[z];
        if (m0 >= count) return;
        if (tid < 128) {
            int idx = m0 + tid;
            int en = (idx < count) ? glist[z * T_ + idx] : -1;
            esm[tid] = en;
            tok[tid] = (en >= 0) ? (en >> 1) : 0;
        }
        __syncthreads();
    }
    if constexpr (MODE == M_SCORES) {
        // precomputed additive mask term for this CTA's 128 kv cols
        if (tid < 128) s_row[tid] = (1.0f - gw[(size_t)(z >> 4) * S_ + n0 + tid]) * (-10000.0f);
    }
    if constexpr (MODE == M_CTX) {
        if (tid < 128) s_row[tid] = 1.0f / g_L[(size_t)z * S_ + m0 + tid];
    }

    int wid = tid >> 5, lane = tid & 31;
    int wm = wid & 1, wn = wid >> 1, g = lane >> 2, tig = lane & 3;
    u32 smb = s2u(dsm);

    // per-thread loader pointers: rows cr and cr+64, seg = tid&3
    int cr = tid >> 2, seg = tid & 3;
    int ra0 = cr, ra1 = cr + 64;
    long ga0 = USETOK ? (long)tok[ra0] : ra0;
    long ga1 = USETOK ? (long)tok[ra1] : ra1;
    cbf* sAh0 = pAh + ga0 * lda + seg * 8;
    cbf* sAh1 = pAh + ga1 * lda + seg * 8;
    cbf* sAl0 = pAl + ga0 * lda + seg * 8;
    cbf* sAl1 = pAl + ga1 * lda + seg * 8;
    cbf* sBh0 = pBh + (long)ra0 * ldb + seg * 8;
    cbf* sBh1 = pBh + (long)ra1 * ldb + seg * 8;
    cbf* sBl0 = pBl + (long)ra0 * ldb + seg * 8;
    cbf* sBl1 = pBl + (long)ra1 * ldb + seg * 8;
    u32 d0 = swb(ra0, seg), d1 = swb(ra1, seg);

#define LOAD_STAGE(s, ktE) do { u32 st_ = smb + (s) * STG_B; int k_ = (ktE); \
    cpa16(st_ + d0, sAh0 + k_);            cpa16(st_ + d1, sAh1 + k_); \
    cpa16(st_ + PLB + d0, sAl0 + k_);      cpa16(st_ + PLB + d1, sAl1 + k_); \
    cpa16(st_ + 2 * PLB + d0, sBh0 + k_);  cpa16(st_ + 2 * PLB + d1, sBh1 + k_); \
    cpa16(st_ + 3 * PLB + d0, sBl0 + k_);  cpa16(st_ + 3 * PLB + d1, sBl1 + k_); } while (0)

    float acc[4][4][4];
#pragma unroll
    for (int a = 0; a < 4; a++)
#pragma unroll
        for (int b = 0; b < 4; b++)
#pragma unroll
            for (int c = 0; c < 4; c++) acc[a][b][c] = 0.f;

    int nk = K / 32;
    LOAD_STAGE(0, 0);  CPA_COMMIT();
    LOAD_STAGE(1, 32); CPA_COMMIT();

    for (int it = 0; it < nk; it++) {
        CPA_WAIT1();
        __syncthreads();
        // R8 schedule: compute FIRST, then prefetch
        u32 stg = smb + (it % NSTG) * STG_B;
        compute_k16(stg, 0, wm, wn, lane, acc);
        compute_k16(stg, 1, wm, wn, lane, acc);
        if (it + 2 < nk) LOAD_STAGE((it + 2) % NSTG, (it + 2) * 32);
        CPA_COMMIT();
    }
    CPA_WAIT0();
    __syncthreads();

    if constexpr (LORA) {
        // one extra k16: A = SCALING*La (fp32, rows via tok), B = Lb (fp32); segs 0..1
#pragma unroll
        for (int i = 0; i < 2; i++) {
            int f = tid + i * 256;
            int row = f >> 2, kc = (f & 3) * 4;
            size_t ro = (size_t)tok[row] * ldla;
            float4 v = *(const float4*)(La + ro + kc);
            v.x *= SCALING_; v.y *= SCALING_; v.z *= SCALING_; v.w *= SCALING_;
            u32 h0, h1, l0, l1;
            split4(v, h0, h1, l0, l1);
            u32 off = smb + swb(row, kc >> 3) + (kc & 7) * 2;
            asm volatile("st.shared.v2.u32 [%0], {%1,%2};" :: "r"(off), "r"(h0), "r"(h1));
            asm volatile("st.shared.v2.u32 [%0], {%1,%2};" :: "r"(off + PLB), "r"(l0), "r"(l1));
            float4 u = *(const float4*)(Lb + (size_t)row * R_ + kc);
            split4(u, h0, h1, l0, l1);
            asm volatile("st.shared.v2.u32 [%0], {%1,%2};" :: "r"(off + 2 * PLB), "r"(h0), "r"(h1));
            asm volatile("st.shared.v2.u32 [%0], {%1,%2};" :: "r"(off + 3 * PLB), "r"(l0), "r"(l1));
        }
        __syncthreads();
        compute_k16(smb, 0, wm, wn, lane, acc);
    }

    // ---------------- epilogues ----------------
    if constexpr (MODE == M_QKV) {
        if (z < 2) {
            u32* ch = (z == 0) ? g_qs_h : g_ks_h;
            u32* cl = (z == 0) ? g_qs_l : g_ks_l;
            size_t co = (size_t)m0 * H_ + n0;
#pragma unroll
            for (int mf = 0; mf < 4; mf++) {
#pragma unroll
                for (int half = 0; half < 2; half++) {
                    int m = wm * 64 + mf * 16 + g + half * 8;
#pragma unroll
                    for (int nf = 0; nf < 4; nf++) {
                        int n = wn * 32 + nf * 8 + tig * 2;
                        u32 h, l;
                        split2(acc[mf][nf][half * 2 + 0], acc[mf][nf][half * 2 + 1], h, l);
                        size_t ix = (co + (size_t)m * H_ + n) >> 1;
                        ch[ix] = h;
                        cl[ix] = l;
                    }
                }
            }
        } else {
            // V MoE: UNTRANSPOSED coalesced atomic accumulate into g_vt[t][n]
#pragma unroll
            for (int mf = 0; mf < 4; mf++) {
#pragma unroll
                for (int half = 0; half < 2; half++) {
                    int lr = wm * 64 + mf * 16 + g + half * 8;
                    int en = esm[lr];
                    if (en < 0) continue;
                    float w = gw[en];
                    int t = en >> 1;
                    float* p = g_vt + (size_t)t * H_ + n0;
#pragma unroll
                    for (int nf = 0; nf < 4; nf++) {
                        int n = wn * 32 + nf * 8 + tig * 2;
                        atomicAdd(p + n, w * acc[mf][nf][half * 2 + 0]);
                        atomicAdd(p + n + 1, w * acc[mf][nf][half * 2 + 1]);
                    }
                }
            }
        }
    } else if constexpr (GATHER) {
#pragma unroll
        for (int mf = 0; mf < 4; mf++) {
#pragma unroll
            for (int half = 0; half < 2; half++) {
                int lr = wm * 64 + mf * 16 + g + half * 8;
                int en = esm[lr];
                if (en < 0) continue;
                float w = gw[en];
                int t = en >> 1;
#pragma unroll
                for (int nf = 0; nf < 4; nf++) {
                    int n = n0 + wn * 32 + nf * 8 + tig * 2;
                    float* p = Cf + (size_t)t * H_ + n;
                    atomicAdd(p, w * acc[mf][nf][half * 2 + 0]);
                    atomicAdd(p + 1, w * acc[mf][nf][half * 2 + 1]);
                }
            }
        }
    } else if constexpr (MODE == M_SCORES) {
        // exp epilogue: write unnormalized exp(P) planes + atomic row sums
#pragma unroll
        for (int mf = 0; mf < 4; mf++) {
#pragma unroll
            for (int half = 0; half < 2; half++) {
                int r = wm * 64 + mf * 16 + g + half * 8;
                float rs = 0.f;
#pragma unroll
                for (int nf = 0; nf < 4; nf++) {
                    int cn = wn * 32 + nf * 8 + tig * 2;
                    float e0 = __expf(acc[mf][nf][half * 2 + 0] * INV_SQRT_DH + s_row[cn]);
                    float e1 = __expf(acc[mf][nf][half * 2 + 1] * INV_SQRT_DH + s_row[cn + 1]);
                    rs += e0 + e1;
                    u32 h, l;
                    split2(e0, e1, h, l);
                    size_t ix = (coff + (size_t)r * S_ + cn) >> 1;
                    g_Ps_h[ix] = h;
                    g_Ps_l[ix] = l;
                }
                rs += __shfl_xor_sync(0xffffffffu, rs, 1);
                rs += __shfl_xor_sync(0xffffffffu, rs, 2);
                if (tig == 0) atomicAdd(&g_L[(size_t)z * S_ + m0 + r], rs);
            }
        }
    } else if constexpr (MODE == M_CTX) {
#pragma unroll
        for (int mf = 0; mf < 4; mf++) {
#pragma unroll
            for (int half = 0; half < 2; half++) {
                int m = wm * 64 + mf * 16 + g + half * 8;
                float iv = s_row[m];
#pragma unroll
                for (int nf = 0; nf < 4; nf++) {
                    int n = wn * 32 + nf * 8 + tig * 2;
                    u32 h, l;
                    split2(acc[mf][nf][half * 2 + 0] * iv, acc[mf][nf][half * 2 + 1] * iv, h, l);
                    size_t ix = (coff + (size_t)m * ldc + n) >> 1;
                    Ch[ix] = h;
                    Cl[ix] = l;
                }
            }
        }
    } else {  // M_XA: fp32 out
        float* C = Cf + coff;
#pragma unroll
        for (int mf = 0; mf < 4; mf++) {
#pragma unroll
            for (int half = 0; half < 2; half++) {
                int m = wm * 64 + mf * 16 + g + half * 8;
#pragma unroll
                for (int nf = 0; nf < 4; nf++) {
                    int n = wn * 32 + nf * 8 + tig * 2;
                    float2 v = {acc[mf][nf][half * 2 + 0], acc[mf][nf][half * 2 + 1]};
                    *(float2*)(C + (size_t)m * ldc + n) = v;
                }
            }
        }
    }
#undef LOAD_STAGE
}

// ---------------- transpose + split: g_vt [b][s][n] -> vts planes [b*H+n][S] ----------------
__global__ void tsplit_kernel() {
    __shared__ float tile[32][33];
    int bx = blockIdx.x, by = blockIdx.y, bz = blockIdx.z;
    int tx = threadIdx.x & 31, ty = threadIdx.x >> 5;
#pragma unroll
    for (int r = 0; r < 32; r += 8) {
        tile[r + ty][tx] = g_vt[((size_t)(bz * S_ + by * 32 + r + ty)) * H_ + bx * 32 + tx];
    }
    __syncthreads();
#pragma unroll
    for (int r = 0; r < 32; r += 8) {
        int n = r + ty;
        if (tx < 16) {
            float a = tile[2 * tx][n], b = tile[2 * tx + 1][n];
            u32 h, l;
            split2(a, b, h, l);
            size_t ix = (((size_t)(bz * H_ + bx * 32 + n)) * S_ + by * 32) / 2 + tx;
            g_vts_h[ix] = h;
            g_vts_l[ix] = l;
        }
    }
}

// ---------------- split fp32 -> bf16 hi/lo planes (MLP=4 batched) ----------------
__global__ void split_kernel(const float4* __restrict__ src, u32* __restrict__ hi,
                             u32* __restrict__ lo, int n4) {
    int stride = gridDim.x * blockDim.x;
    for (int i = blockIdx.x * blockDim.x + threadIdx.x; i < n4; i += 4 * stride) {
        float4 v[4];
#pragma unroll
        for (int j = 0; j < 4; j++) {
            int idx = i + j * stride;
            if (idx < n4) v[j] = src[idx];
        }
#pragma unroll
        for (int j = 0; j < 4; j++) {
            int idx = i + j * stride;
            if (idx < n4) {
                u32 h0, h1, l0, l1;
                split4(v[j], h0, h1, l0, l1);
                *(uint2*)&hi[(size_t)idx * 2] = make_uint2(h0, h1);
                *(uint2*)&lo[(size_t)idx * 2] = make_uint2(l0, l1);
            }
        }
    }
}

// ---------------- init counts ----------------
__global__ void init_counts_kernel() {
    if (threadIdx.x < E_) {
        g_cnt_v[threadIdx.x] = 0;
        g_cnt_o[threadIdx.x] = 0;
    }
}

// ---------------- routing ----------------
__global__ void routing_kernel(const float* __restrict__ x,
                               const float* __restrict__ gv,
                               const float* __restrict__ go) {
    int t = blockIdx.x;
    const float* xt = x + (size_t)t * H_;
    float pv[E_], po[E_];
#pragma unroll
    for (int e = 0; e < E_; e++) { pv[e] = 0.f; po[e] = 0.f; }
    for (int k = threadIdx.x; k < H_; k += 128) {
        float xv = xt[k];
#pragma unroll
        for (int e = 0; e < E_; e++) {
            pv[e] += xv * gv[e * H_ + k];
            po[e] += xv * go[e * H_ + k];
        }
    }
    __shared__ float red[2 * E_][128];
#pragma unroll
    for (int e = 0; e < E_; e++) {
        red[e][threadIdx.x] = pv[e];
        red[E_ + e][threadIdx.x] = po[e];
    }
    __syncthreads();
    if (threadIdx.x < 2 * E_) {
        float s = 0.f;
        for (int i = 0; i < 128; i++) s += red[threadIdx.x][i];
        red[threadIdx.x][0] = s;
    }
    __syncthreads();
    if (threadIdx.x < 2) {
        bool isO = (threadIdx.x == 1);
        float sc[E_];
#pragma unroll
        for (int e = 0; e < E_; e++) {
            float d = red[(isO ? E_ : 0) + e][0];
            sc[e] = 1.f / (1.f + expf(-d));
        }
        int e0 = 0;
        for (int e = 1; e < E_; e++) if (sc[e] > sc[e0]) e0 = e;
        int e1 = -1;
        for (int e = 0; e < E_; e++) {
            if (e == e0) continue;
            if (e1 < 0 || sc[e] > sc[e1]) e1 = e;
        }
        float t1 = expf(sc[e1] - sc[e0]);
        float w0 = 1.f / (1.f + t1);
        float w1 = t1 / (1.f + t1);
        if (!isO) {
            g_wslot_v[t * 2 + 0] = w0;
            g_wslot_v[t * 2 + 1] = w1;
            int p0 = atomicAdd(&g_cnt_v[e0], 1); g_list_v[e0 * T_ + p0] = t * 2 + 0;
            int p1 = atomicAdd(&g_cnt_v[e1], 1); g_list_v[e1 * T_ + p1] = t * 2 + 1;
        } else {
            g_wslot_o[t * 2 + 0] = w0;
            g_wslot_o[t * 2 + 1] = w1;
            int p0 = atomicAdd(&g_cnt_o[e0], 1); g_list_o[e0 * T_ + p0] = t * 2 + 0;
            int p1 = atomicAdd(&g_cnt_o[e1], 1); g_list_o[e1 * T_ + p1] = t * 2 + 1;
        }
    }
}

// ---------------- launcher ----------------
extern "C" void kernel_launch(void* const* d_in, const int* in_sizes, int n_in,
                              void* d_out, int out_size) {
    const float* x      = (const float*)d_in[0];
    const float* amask  = (const float*)d_in[1];
    const float* wq     = (const float*)d_in[2];
    const float* wk     = (const float*)d_in[3];
    const float* q_a    = (const float*)d_in[4];
    const float* q_b    = (const float*)d_in[5];
    const float* k_a    = (const float*)d_in[6];
    const float* k_b    = (const float*)d_in[7];
    const float* gv     = (const float*)d_in[8];
    const float* go     = (const float*)d_in[9];
    const float* v_base = (const float*)d_in[10];
    const float* v_a    = (const float*)d_in[11];
    const float* v_b    = (const float*)d_in[12];
    const float* o_base = (const float*)d_in[13];
    const float* o_a    = (const float*)d_in[14];
    const float* o_b    = (const float*)d_in[15];
    float* out = (float*)d_out;

#define SYM(v, s) void* v; cudaGetSymbolAddress(&v, s)
    SYM(p_vt, g_vt); SYM(p_L, g_L); SYM(p_xacat, g_xacat); SYM(p_xao, g_xao);
    SYM(p_wcat, g_wcat); SYM(p_wcat2, g_wcat2);
    SYM(p_list_v, g_list_v); SYM(p_list_o, g_list_o);
    SYM(p_cnt_v, g_cnt_v); SYM(p_cnt_o, g_cnt_o);
    SYM(p_ws_v, g_wslot_v); SYM(p_ws_o, g_wslot_o);
    SYM(xs_h, g_xs_h); SYM(xs_l, g_xs_l);
    SYM(qs_h, g_qs_h); SYM(qs_l, g_qs_l);
    SYM(ks_h, g_ks_h); SYM(ks_l, g_ks_l);
    SYM(cts_h, g_cts_h); SYM(cts_l, g_cts_l);
    SYM(vts_h, g_vts_h); SYM(vts_l, g_vts_l);
    SYM(Ps_h, g_Ps_h); SYM(Ps_l, g_Ps_l);
    SYM(wqs_h, g_wqs_h); SYM(wqs_l, g_wqs_l);
    SYM(wks_h, g_wks_h); SYM(wks_l, g_wks_l);
    SYM(vbs_h, g_vbs_h); SYM(vbs_l, g_vbs_l);
    SYM(obs_h, g_obs_h); SYM(obs_l, g_obs_l);
    SYM(wcs_h, g_wcs_h); SYM(wcs_l, g_wcs_l);
    SYM(wcs2_h, g_wcs2_h); SYM(wcs2_l, g_wcs2_l);
#undef SYM

    cudaFuncSetAttribute(tc_gemm<M_XA>,     cudaFuncAttributeMaxDynamicSharedMemorySize, SMEM_SZ);
    cudaFuncSetAttribute(tc_gemm<M_MOE>,    cudaFuncAttributeMaxDynamicSharedMemorySize, SMEM_SZ);
    cudaFuncSetAttribute(tc_gemm<M_QKV>,    cudaFuncAttributeMaxDynamicSharedMemorySize, SMEM_SZ);
    cudaFuncSetAttribute(tc_gemm<M_SCORES>, cudaFuncAttributeMaxDynamicSharedMemorySize, SMEM_SZ);
    cudaFuncSetAttribute(tc_gemm<M_CTX>,    cudaFuncAttributeMaxDynamicSharedMemorySize, SMEM_SZ);

    // LoRA-A weight concats (fp32)
    cudaMemcpyAsync((float*)p_wcat,           q_a, sizeof(float) * R_ * H_,      cudaMemcpyDeviceToDevice);
    cudaMemcpyAsync((float*)p_wcat + 16 * H_, k_a, sizeof(float) * R_ * H_,      cudaMemcpyDeviceToDevice);
    cudaMemcpyAsync((float*)p_wcat + 32 * H_, v_a, sizeof(float) * E_ * R_ * H_, cudaMemcpyDeviceToDevice);
    cudaMemcpyAsync((float*)p_wcat2,          o_a, sizeof(float) * E_ * R_ * H_, cudaMemcpyDeviceToDevice);

    cudaMemsetAsync(p_vt, 0, sizeof(float) * (size_t)T_ * H_);
    cudaMemsetAsync(p_L, 0, sizeof(float) * (size_t)B_ * NH_ * S_);
    cudaMemsetAsync(out, 0, sizeof(float) * (size_t)T_ * H_);
    init_counts_kernel<<<1, 32>>>();
    routing_kernel<<<T_, 128>>>(x, gv, go);

    // splits: inputs + weights (MLP=4 batched)
    split_kernel<<<1024, 256>>>((const float4*)x,      (u32*)xs_h,  (u32*)xs_l,  T_ * H_ / 4);
    split_kernel<<<1024, 256>>>((const float4*)wq,     (u32*)wqs_h, (u32*)wqs_l, H_ * H_ / 4);
    split_kernel<<<1024, 256>>>((const float4*)wk,     (u32*)wks_h, (u32*)wks_l, H_ * H_ / 4);
    split_kernel<<<2048, 256>>>((const float4*)v_base, (u32*)vbs_h, (u32*)vbs_l, E_ * H_ * H_ / 4);
    split_kernel<<<2048, 256>>>((const float4*)o_base, (u32*)obs_h, (u32*)obs_l, E_ * H_ * H_ / 4);
    split_kernel<<<256, 256>>>((const float4*)p_wcat,  (u32*)wcs_h, (u32*)wcs_l, 128 * H_ / 4);
    split_kernel<<<256, 256>>>((const float4*)p_wcat2, (u32*)wcs2_h, (u32*)wcs2_l, 128 * H_ / 4);

    // XA: xacat = x @ wcat^T (fp32 out)
    tc_gemm<M_XA><<<dim3(1, T_ / 128), 256, SMEM_SZ>>>(
        (cbf*)xs_h, (cbf*)xs_l, (cbf*)wcs_h, (cbf*)wcs_l,
        (float*)p_xacat, nullptr, nullptr, nullptr, nullptr, nullptr, nullptr, nullptr,
        nullptr, nullptr);

    // fused Q-proj (z=0), K-proj (z=1), V-MoE (z=2..7, untransposed atomic V)
    tc_gemm<M_QKV><<<dim3(H_ / 128, T_ / 128, 2 + E_), 256, SMEM_SZ>>>(
        nullptr, nullptr, nullptr, nullptr,
        nullptr, nullptr, nullptr,
        nullptr, q_b,
        (const int*)p_list_v, (const int*)p_cnt_v, (const float*)p_ws_v,
        k_b, v_b);

    // transpose + split V -> vts planes
    tsplit_kernel<<<dim3(H_ / 32, S_ / 32, B_), 256>>>();

    // attention: scores with fused exp + row-sum epilogue, then ctx with 1/L epilogue
    tc_gemm<M_SCORES><<<dim3(S_ / 128, S_ / 128, B_ * NH_), 256, SMEM_SZ>>>(
        (cbf*)qs_h, (cbf*)qs_l, (cbf*)ks_h, (cbf*)ks_l,
        nullptr, nullptr, nullptr, nullptr, nullptr, nullptr, nullptr, amask,
        nullptr, nullptr);
    tc_gemm<M_CTX><<<dim3(1, S_ / 128, B_ * NH_), 256, SMEM_SZ>>>(
        (cbf*)Ps_h, (cbf*)Ps_l, (cbf*)vts_h, (cbf*)vts_l,
        nullptr, (u32*)cts_h, (u32*)cts_l, nullptr, nullptr, nullptr, nullptr, nullptr,
        nullptr, nullptr);

    // O path
    tc_gemm<M_XA><<<dim3(1, T_ / 128), 256, SMEM_SZ>>>(
        (cbf*)cts_h, (cbf*)cts_l, (cbf*)wcs2_h, (cbf*)wcs2_l,
        (float*)p_xao, nullptr, nullptr, nullptr, nullptr, nullptr, nullptr, nullptr,
        nullptr, nullptr);
    tc_gemm<M_MOE><<<dim3(H_ / 128, T_ / 128, E_), 256, SMEM_SZ>>>(
        (cbf*)cts_h, (cbf*)cts_l, (cbf*)obs_h, (cbf*)obs_l,
        out, nullptr, nullptr, (const float*)p_xao, o_b,
        (const int*)p_list_o, (const int*)p_cnt_o, (const float*)p_ws_o,
        nullptr, nullptr);
}

// round 16
// speedup vs baseline: 1.0852x; 1.0560x over previous
#include <cuda_runtime.h>
#include <cuda_bf16.h>
#include <math.h>

typedef unsigned int u32;
typedef unsigned long long u64;

// ---------------- problem constants ----------------
#define B_   2
#define S_   2048
#define H_   2048
#define NH_  16
#define DH_  128
#define E_   6
#define R_   16
#define T_   (B_ * S_)            // 4096 tokens
#define SCALING_ 8.0f
#define INV_SQRT_DH 0.08838834764831845f

// tile: 128 rows x 32 bf16 = 64B/row, XOR-swizzled. 8KB per plane.
#define PLB 8192
#define STG_B (4 * PLB)           // Ahi, Alo, Bhi, Blo = 32KB
#define NSTG 3
#define SMEM_SZ (NSTG * STG_B)    // 96KB

// ---------------- scratch: fp32 ----------------
__device__ float g_vslot[2 * T_ * H_]; // V per-slot rows [en][n], written exactly once
__device__ float g_L[B_ * NH_ * S_];   // unnormalized softmax row sums
__device__ float g_xacat[T_ * 128];
__device__ float g_xao[T_ * 128];
__device__ float g_wcat[128 * H_];
__device__ float g_wcat2[128 * H_];
__device__ int   g_list_v[E_ * T_];
__device__ int   g_list_o[E_ * T_];
__device__ int   g_cnt_v[E_];
__device__ int   g_cnt_o[E_];
__device__ float g_wslot_v[T_ * 2];
__device__ float g_wslot_o[T_ * 2];

// ---------------- scratch: bf16 hi/lo planes (u32 = 2 bf16) ----------------
#define PT (T_ * H_ / 2)
#define PW (H_ * H_ / 2)
#define PE (E_ * H_ * H_ / 2)
#define PC (128 * H_ / 2)
__device__ u32 g_xs_h[PT],  g_xs_l[PT];
__device__ u32 g_qs_h[PT],  g_qs_l[PT];
__device__ u32 g_ks_h[PT],  g_ks_l[PT];
__device__ u32 g_cts_h[PT], g_cts_l[PT];
__device__ u32 g_vts_h[PT], g_vts_l[PT];   // V transposed planes [b*H+n][S]
__device__ u32 g_Ps_h[(size_t)B_ * NH_ * S_ * S_ / 2];
__device__ u32 g_Ps_l[(size_t)B_ * NH_ * S_ * S_ / 2];
__device__ u32 g_wqs_h[PW], g_wqs_l[PW];
__device__ u32 g_wks_h[PW], g_wks_l[PW];
__device__ u32 g_vbs_h[PE], g_vbs_l[PE];
__device__ u32 g_obs_h[PE], g_obs_l[PE];
__device__ u32 g_wcs_h[PC], g_wcs_l[PC];
__device__ u32 g_wcs2_h[PC], g_wcs2_l[PC];

// ---------------- helpers ----------------
__device__ __forceinline__ u32 s2u(const void* p) {
    u32 a;
    asm("{ .reg .u64 t; cvta.to.shared.u64 t, %1; cvt.u32.u64 %0, t; }" : "=r"(a) : "l"(p));
    return a;
}
__device__ __forceinline__ u32 pack_bf2(float a, float b) {
    __nv_bfloat162 t = __floats2bfloat162_rn(a, b);
    return *reinterpret_cast<u32*>(&t);
}
__device__ __forceinline__ void split4(float4 v, u32& h0, u32& h1, u32& l0, u32& l1) {
    __nv_bfloat162 p0 = __floats2bfloat162_rn(v.x, v.y);
    __nv_bfloat162 p1 = __floats2bfloat162_rn(v.z, v.w);
    h0 = *reinterpret_cast<u32*>(&p0);
    h1 = *reinterpret_cast<u32*>(&p1);
    l0 = pack_bf2(v.x - __low2float(p0), v.y - __high2float(p0));
    l1 = pack_bf2(v.z - __low2float(p1), v.w - __high2float(p1));
}
__device__ __forceinline__ void split2(float a, float b, u32& h, u32& l) {
    __nv_bfloat162 p = __floats2bfloat162_rn(a, b);
    h = *reinterpret_cast<u32*>(&p);
    l = pack_bf2(a - __low2float(p), b - __high2float(p));
}
__device__ __forceinline__ void mma_bf16(float* c, u32 a0, u32 a1, u32 a2, u32 a3, u32 b0, u32 b1) {
    asm volatile(
        "mma.sync.aligned.m16n8k16.row.col.f32.bf16.bf16.f32 "
        "{%0,%1,%2,%3}, {%4,%5,%6,%7}, {%8,%9}, {%0,%1,%2,%3};"
        : "+f"(c[0]), "+f"(c[1]), "+f"(c[2]), "+f"(c[3])
        : "r"(a0), "r"(a1), "r"(a2), "r"(a3), "r"(b0), "r"(b1));
}
__device__ __forceinline__ void ldsm4(u32* r, u32 a) {
    asm volatile("ldmatrix.sync.aligned.m8n8.x4.shared.b16 {%0,%1,%2,%3}, [%4];"
        : "=r"(r[0]), "=r"(r[1]), "=r"(r[2]), "=r"(r[3]) : "r"(a));
}
__device__ __forceinline__ void cpa16(u32 dst, const void* src) {
    asm volatile("cp.async.ca.shared.global [%0], [%1], 16;" :: "r"(dst), "l"(src));
}
#define CPA_COMMIT() asm volatile("cp.async.commit_group;" ::: "memory")
#define CPA_WAIT1()  asm volatile("cp.async.wait_group 1;" ::: "memory")
#define CPA_WAIT0()  asm volatile("cp.async.wait_group 0;" ::: "memory")
// XOR swizzle: row 64B, seg = 16B chunk idx (0..3)
__device__ __forceinline__ u32 swb(int row, int seg) {
    return (u32)(row * 64 + ((seg ^ ((row >> 1) & 3)) * 16));
}

// one k16 MMA step over 128x128 tile (3-term bf16 split), stage base = stg
__device__ __forceinline__ void compute_k16(u32 stg, int ks, int wm, int wn, int lane,
                                            float (&acc)[4][4][4]) {
    int j = lane >> 3, r7 = lane & 7;
    int rowA = wm * 64 + (j & 1) * 8 + r7;
    int segA = ks * 2 + (j >> 1);
    u32 aH = stg + swb(rowA, segA);
    u32 aL = aH + PLB;
    int rowB = wn * 32 + (j >> 1) * 8 + r7;
    int segB = ks * 2 + (j & 1);
    u32 bH = stg + 2 * PLB + swb(rowB, segB);
    u32 bL = bH + PLB;

    u32 bh[2][4], bl[2][4], am[4][4];
    ldsm4(bh[0], bH); ldsm4(bh[1], bH + 1024);
    ldsm4(bl[0], bL); ldsm4(bl[1], bL + 1024);
#pragma unroll
    for (int mf = 0; mf < 4; mf++) ldsm4(am[mf], aH + mf * 1024);
#pragma unroll
    for (int mf = 0; mf < 4; mf++)
#pragma unroll
        for (int nf = 0; nf < 4; nf++) {
            const u32* b = &bh[nf >> 1][(nf & 1) * 2];
            mma_bf16(acc[mf][nf], am[mf][0], am[mf][1], am[mf][2], am[mf][3], b[0], b[1]);
        }
#pragma unroll
    for (int mf = 0; mf < 4; mf++)
#pragma unroll
        for (int nf = 0; nf < 4; nf++) {
            const u32* b = &bl[nf >> 1][(nf & 1) * 2];
            mma_bf16(acc[mf][nf], am[mf][0], am[mf][1], am[mf][2], am[mf][3], b[0], b[1]);
        }
#pragma unroll
    for (int mf = 0; mf < 4; mf++) ldsm4(am[mf], aL + mf * 1024);
#pragma unroll
    for (int mf = 0; mf < 4; mf++)
#pragma unroll
        for (int nf = 0; nf < 4; nf++) {
            const u32* b = &bh[nf >> 1][(nf & 1) * 2];
            mma_bf16(acc[mf][nf], am[mf][0], am[mf][1], am[mf][2], am[mf][3], b[0], b[1]);
        }
}

// ---------------- the one NT GEMM kernel ----------------
enum { M_XA = 1, M_MOE = 2, M_SCORES = 4, M_CTX = 5, M_QKV = 6 };

typedef const __nv_bfloat16 cbf;

template <int MODE>
__global__ void __launch_bounds__(256) tc_gemm(
    cbf* Ah_, cbf* Al_, cbf* Bh_, cbf* Bl_,
    float* __restrict__ Cf, u32* __restrict__ Ch, u32* __restrict__ Cl,
    const float* __restrict__ Lab, const float* __restrict__ Lbb,
    const int* __restrict__ glist, const int* __restrict__ gcnt,
    const float* __restrict__ gw,
    const float* __restrict__ Lb2, const float* __restrict__ Lb3) {
    constexpr bool GATHER = (MODE == M_MOE);
    constexpr bool QKV = (MODE == M_QKV);
    constexpr bool LORA = (MODE == M_MOE || MODE == M_QKV);
    constexpr bool USETOK = (GATHER || QKV);
    extern __shared__ __align__(16) unsigned char dsm[];
    __shared__ int esm[128];
    __shared__ int tok[128];
    __shared__ float s_row[128];

    int tid = threadIdx.x;
    int m0 = blockIdx.y * 128, n0 = blockIdx.x * 128, z = blockIdx.z;

    cbf *pAh, *pAl, *pBh, *pBl;
    const float* La = nullptr;
    const float* Lb = nullptr;
    long lda, ldb, ldc = 0;
    int K, ldla = 0;
    size_t coff = 0;

    if constexpr (MODE == M_XA) {
        // K-split along blockIdx.x: 4 chunks of 512
        int kxo = blockIdx.x * 512;
        pAh = Ah_ + (size_t)m0 * H_ + kxo; pAl = Al_ + (size_t)m0 * H_ + kxo;
        pBh = Bh_ + kxo; pBl = Bl_ + kxo;
        coff = (size_t)m0 * 128;
        lda = ldb = H_; ldc = 128; K = 512;
    } else if constexpr (MODE == M_MOE) {
        pAh = Ah_; pAl = Al_;
        pBh = Bh_ + (size_t)z * H_ * H_ + (size_t)n0 * H_;
        pBl = Bl_ + (size_t)z * H_ * H_ + (size_t)n0 * H_;
        lda = ldb = H_; K = H_;
        La = Lab + z * R_; ldla = 128;
        Lb = Lbb + (size_t)z * H_ * R_ + (size_t)n0 * R_;
    } else if constexpr (MODE == M_QKV) {
        pAh = (cbf*)g_xs_h; pAl = (cbf*)g_xs_l;
        size_t bo = (size_t)n0 * H_;
        if (z == 0)      { pBh = (cbf*)g_wqs_h + bo; pBl = (cbf*)g_wqs_l + bo; }
        else if (z == 1) { pBh = (cbf*)g_wks_h + bo; pBl = (cbf*)g_wks_l + bo; }
        else {
            size_t eo = (size_t)(z - 2) * H_ * H_;
            pBh = (cbf*)g_vbs_h + eo + bo; pBl = (cbf*)g_vbs_l + eo + bo;
        }
        lda = ldb = H_; K = H_; ldla = 128;
        La = g_xacat + (z == 0 ? 0 : (z == 1 ? 16 : 32 + (z - 2) * R_));
        Lb = (z == 0 ? Lbb : (z == 1 ? Lb2 : Lb3 + (size_t)(z - 2) * H_ * R_)) + (size_t)n0 * R_;
    } else if constexpr (MODE == M_SCORES) {
        int b = z >> 4, h = z & 15;
        size_t ao = ((size_t)b * S_ + m0) * H_ + h * DH_;
        size_t bo = ((size_t)b * S_ + n0) * H_ + h * DH_;
        pAh = Ah_ + ao; pAl = Al_ + ao;
        pBh = Bh_ + bo; pBl = Bl_ + bo;
        coff = (size_t)z * S_ * S_ + (size_t)m0 * S_ + n0;
        lda = ldb = H_; ldc = S_; K = DH_;
    } else {  // M_CTX
        size_t ao = (size_t)z * S_ * S_ + (size_t)m0 * S_;
        size_t bo = (size_t)z * DH_ * S_;
        pAh = Ah_ + ao; pAl = Al_ + ao;
        pBh = Bh_ + bo; pBl = Bl_ + bo;
        int b = z >> 4, h = z & 15;
        coff = ((size_t)b * S_ + m0) * H_ + h * DH_;
        lda = S_; ldb = S_; ldc = H_; K = S_;
    }

    if constexpr (MODE == M_QKV) {
        if (z >= 2 && m0 >= gcnt[z - 2]) return;
        if (tid < 128) {
            if (z < 2) { tok[tid] = m0 + tid; esm[tid] = 0; }
            else {
                int count = gcnt[z - 2];
                int idx = m0 + tid;
                int en = (idx < count) ? glist[(z - 2) * T_ + idx] : -1;
                esm[tid] = en;
                tok[tid] = (en >= 0) ? (en >> 1) : 0;
            }
        }
        __syncthreads();
    } else if constexpr (GATHER) {
        int count = gcnt[z];
        if (m0 >= count) return;
        if (tid < 128) {
            int idx = m0 + tid;
            int en = (idx < count) ? glist[z * T_ + idx] : -1;
            esm[tid] = en;
            tok[tid] = (en >= 0) ? (en >> 1) : 0;
        }
        __syncthreads();
    }
    if constexpr (MODE == M_SCORES) {
        if (tid < 128) s_row[tid] = (1.0f - gw[(size_t)(z >> 4) * S_ + n0 + tid]) * (-10000.0f);
    }
    if constexpr (MODE == M_CTX) {
        if (tid < 128) s_row[tid] = 1.0f / g_L[(size_t)z * S_ + m0 + tid];
    }

    int wid = tid >> 5, lane = tid & 31;
    int wm = wid & 1, wn = wid >> 1, g = lane >> 2, tig = lane & 3;
    u32 smb = s2u(dsm);

    // per-thread loader pointers: rows cr and cr+64, seg = tid&3
    int cr = tid >> 2, seg = tid & 3;
    int ra0 = cr, ra1 = cr + 64;
    long ga0 = USETOK ? (long)tok[ra0] : ra0;
    long ga1 = USETOK ? (long)tok[ra1] : ra1;
    cbf* sAh0 = pAh + ga0 * lda + seg * 8;
    cbf* sAh1 = pAh + ga1 * lda + seg * 8;
    cbf* sAl0 = pAl + ga0 * lda + seg * 8;
    cbf* sAl1 = pAl + ga1 * lda + seg * 8;
    cbf* sBh0 = pBh + (long)ra0 * ldb + seg * 8;
    cbf* sBh1 = pBh + (long)ra1 * ldb + seg * 8;
    cbf* sBl0 = pBl + (long)ra0 * ldb + seg * 8;
    cbf* sBl1 = pBl + (long)ra1 * ldb + seg * 8;
    u32 d0 = swb(ra0, seg), d1 = swb(ra1, seg);

#define LOAD_STAGE(s, ktE) do { u32 st_ = smb + (s) * STG_B; int k_ = (ktE); \
    cpa16(st_ + d0, sAh0 + k_);            cpa16(st_ + d1, sAh1 + k_); \
    cpa16(st_ + PLB + d0, sAl0 + k_);      cpa16(st_ + PLB + d1, sAl1 + k_); \
    cpa16(st_ + 2 * PLB + d0, sBh0 + k_);  cpa16(st_ + 2 * PLB + d1, sBh1 + k_); \
    cpa16(st_ + 3 * PLB + d0, sBl0 + k_);  cpa16(st_ + 3 * PLB + d1, sBl1 + k_); } while (0)

    float acc[4][4][4];
#pragma unroll
    for (int a = 0; a < 4; a++)
#pragma unroll
        for (int b = 0; b < 4; b++)
#pragma unroll
            for (int c = 0; c < 4; c++) acc[a][b][c] = 0.f;

    int nk = K / 32;
    LOAD_STAGE(0, 0);  CPA_COMMIT();
    LOAD_STAGE(1, 32); CPA_COMMIT();

    for (int it = 0; it < nk; it++) {
        CPA_WAIT1();
        __syncthreads();
        // R8 schedule: compute FIRST, then prefetch
        u32 stg = smb + (it % NSTG) * STG_B;
        compute_k16(stg, 0, wm, wn, lane, acc);
        compute_k16(stg, 1, wm, wn, lane, acc);
        if (it + 2 < nk) LOAD_STAGE((it + 2) % NSTG, (it + 2) * 32);
        CPA_COMMIT();
    }
    CPA_WAIT0();
    __syncthreads();

    if constexpr (LORA) {
        // one extra k16: A = SCALING*La (fp32, rows via tok), B = Lb (fp32); segs 0..1
#pragma unroll
        for (int i = 0; i < 2; i++) {
            int f = tid + i * 256;
            int row = f >> 2, kc = (f & 3) * 4;
            size_t ro = (size_t)tok[row] * ldla;
            float4 v = *(const float4*)(La + ro + kc);
            v.x *= SCALING_; v.y *= SCALING_; v.z *= SCALING_; v.w *= SCALING_;
            u32 h0, h1, l0, l1;
            split4(v, h0, h1, l0, l1);
            u32 off = smb + swb(row, kc >> 3) + (kc & 7) * 2;
            asm volatile("st.shared.v2.u32 [%0], {%1,%2};" :: "r"(off), "r"(h0), "r"(h1));
            asm volatile("st.shared.v2.u32 [%0], {%1,%2};" :: "r"(off + PLB), "r"(l0), "r"(l1));
            float4 u = *(const float4*)(Lb + (size_t)row * R_ + kc);
            split4(u, h0, h1, l0, l1);
            asm volatile("st.shared.v2.u32 [%0], {%1,%2};" :: "r"(off + 2 * PLB), "r"(h0), "r"(h1));
            asm volatile("st.shared.v2.u32 [%0], {%1,%2};" :: "r"(off + 3 * PLB), "r"(l0), "r"(l1));
        }
        __syncthreads();
        compute_k16(smb, 0, wm, wn, lane, acc);
    }

    // ---------------- epilogues ----------------
    if constexpr (MODE == M_QKV) {
        if (z < 2) {
            u32* ch = (z == 0) ? g_qs_h : g_ks_h;
            u32* cl = (z == 0) ? g_qs_l : g_ks_l;
            size_t co = (size_t)m0 * H_ + n0;
#pragma unroll
            for (int mf = 0; mf < 4; mf++) {
#pragma unroll
                for (int half = 0; half < 2; half++) {
                    int m = wm * 64 + mf * 16 + g + half * 8;
#pragma unroll
                    for (int nf = 0; nf < 4; nf++) {
                        int n = wn * 32 + nf * 8 + tig * 2;
                        u32 h, l;
                        split2(acc[mf][nf][half * 2 + 0], acc[mf][nf][half * 2 + 1], h, l);
                        size_t ix = (co + (size_t)m * H_ + n) >> 1;
                        ch[ix] = h;
                        cl[ix] = l;
                    }
                }
            }
        } else {
            // V MoE: non-atomic per-slot stores (each slot row written exactly once)
#pragma unroll
            for (int mf = 0; mf < 4; mf++) {
#pragma unroll
                for (int half = 0; half < 2; half++) {
                    int lr = wm * 64 + mf * 16 + g + half * 8;
                    int en = esm[lr];
                    if (en < 0) continue;
                    float w = gw[en];
                    float* p = g_vslot + (size_t)en * H_ + n0;
#pragma unroll
                    for (int nf = 0; nf < 4; nf++) {
                        int n = wn * 32 + nf * 8 + tig * 2;
                        float2 v = {w * acc[mf][nf][half * 2 + 0], w * acc[mf][nf][half * 2 + 1]};
                        *(float2*)(p + n) = v;
                    }
                }
            }
        }
    } else if constexpr (GATHER) {
#pragma unroll
        for (int mf = 0; mf < 4; mf++) {
#pragma unroll
            for (int half = 0; half < 2; half++) {
                int lr = wm * 64 + mf * 16 + g + half * 8;
                int en = esm[lr];
                if (en < 0) continue;
                float w = gw[en];
                int t = en >> 1;
#pragma unroll
                for (int nf = 0; nf < 4; nf++) {
                    int n = n0 + wn * 32 + nf * 8 + tig * 2;
                    float* p = Cf + (size_t)t * H_ + n;
                    atomicAdd(p, w * acc[mf][nf][half * 2 + 0]);
                    atomicAdd(p + 1, w * acc[mf][nf][half * 2 + 1]);
                }
            }
        }
    } else if constexpr (MODE == M_SCORES) {
        // exp epilogue: write unnormalized exp(P) planes + atomic row sums
#pragma unroll
        for (int mf = 0; mf < 4; mf++) {
#pragma unroll
            for (int half = 0; half < 2; half++) {
                int r = wm * 64 + mf * 16 + g + half * 8;
                float rs = 0.f;
#pragma unroll
                for (int nf = 0; nf < 4; nf++) {
                    int cn = wn * 32 + nf * 8 + tig * 2;
                    float e0 = __expf(acc[mf][nf][half * 2 + 0] * INV_SQRT_DH + s_row[cn]);
                    float e1 = __expf(acc[mf][nf][half * 2 + 1] * INV_SQRT_DH + s_row[cn + 1]);
                    rs += e0 + e1;
                    u32 h, l;
                    split2(e0, e1, h, l);
                    size_t ix = (coff + (size_t)r * S_ + cn) >> 1;
                    g_Ps_h[ix] = h;
                    g_Ps_l[ix] = l;
                }
                rs += __shfl_xor_sync(0xffffffffu, rs, 1);
                rs += __shfl_xor_sync(0xffffffffu, rs, 2);
                if (tig == 0) atomicAdd(&g_L[(size_t)z * S_ + m0 + r], rs);
            }
        }
    } else if constexpr (MODE == M_CTX) {
#pragma unroll
        for (int mf = 0; mf < 4; mf++) {
#pragma unroll
            for (int half = 0; half < 2; half++) {
                int m = wm * 64 + mf * 16 + g + half * 8;
                float iv = s_row[m];
#pragma unroll
                for (int nf = 0; nf < 4; nf++) {
                    int n = wn * 32 + nf * 8 + tig * 2;
                    u32 h, l;
                    split2(acc[mf][nf][half * 2 + 0] * iv, acc[mf][nf][half * 2 + 1] * iv, h, l);
                    size_t ix = (coff + (size_t)m * ldc + n) >> 1;
                    Ch[ix] = h;
                    Cl[ix] = l;
                }
            }
        }
    } else {  // M_XA: fp32 atomic accumulate (K-split partials)
        float* C = Cf + coff;
#pragma unroll
        for (int mf = 0; mf < 4; mf++) {
#pragma unroll
            for (int half = 0; half < 2; half++) {
                int m = wm * 64 + mf * 16 + g + half * 8;
#pragma unroll
                for (int nf = 0; nf < 4; nf++) {
                    int n = wn * 32 + nf * 8 + tig * 2;
                    atomicAdd(C + (size_t)m * ldc + n, acc[mf][nf][half * 2 + 0]);
                    atomicAdd(C + (size_t)m * ldc + n + 1, acc[mf][nf][half * 2 + 1]);
                }
            }
        }
    }
#undef LOAD_STAGE
}

// ---------------- transpose + split: g_vslot [2 rows per t] -> vts planes [b*H+n][S] ----------------
__global__ void tsplit_kernel() {
    __shared__ float tile[32][33];
    int bx = blockIdx.x, by = blockIdx.y, bz = blockIdx.z;
    int tx = threadIdx.x & 31, ty = threadIdx.x >> 5;
#pragma unroll
    for (int r = 0; r < 32; r += 8) {
        size_t t = (size_t)(bz * S_ + by * 32 + r + ty);
        int col = bx * 32 + tx;
        tile[r + ty][tx] = g_vslot[(2 * t) * H_ + col] + g_vslot[(2 * t + 1) * H_ + col];
    }
    __syncthreads();
#pragma unroll
    for (int r = 0; r < 32; r += 8) {
        int n = r + ty;
        if (tx < 16) {
            float a = tile[2 * tx][n], b = tile[2 * tx + 1][n];
            u32 h, l;
            split2(a, b, h, l);
            size_t ix = (((size_t)(bz * H_ + bx * 32 + n)) * S_ + by * 32) / 2 + tx;
            g_vts_h[ix] = h;
            g_vts_l[ix] = l;
        }
    }
}

// ---------------- split fp32 -> bf16 hi/lo planes (MLP=4 batched) ----------------
__global__ void split_kernel(const float4* __restrict__ src, u32* __restrict__ hi,
                             u32* __restrict__ lo, int n4) {
    int stride = gridDim.x * blockDim.x;
    for (int i = blockIdx.x * blockDim.x + threadIdx.x; i < n4; i += 4 * stride) {
        float4 v[4];
#pragma unroll
        for (int j = 0; j < 4; j++) {
            int idx = i + j * stride;
            if (idx < n4) v[j] = src[idx];
        }
#pragma unroll
        for (int j = 0; j < 4; j++) {
            int idx = i + j * stride;
            if (idx < n4) {
                u32 h0, h1, l0, l1;
                split4(v[j], h0, h1, l0, l1);
                *(uint2*)&hi[(size_t)idx * 2] = make_uint2(h0, h1);
                *(uint2*)&lo[(size_t)idx * 2] = make_uint2(l0, l1);
            }
        }
    }
}

// ---------------- init counts ----------------
__global__ void init_counts_kernel() {
    if (threadIdx.x < E_) {
        g_cnt_v[threadIdx.x] = 0;
        g_cnt_o[threadIdx.x] = 0;
    }
}

// ---------------- routing ----------------
__global__ void routing_kernel(const float* __restrict__ x,
                               const float* __restrict__ gv,
                               const float* __restrict__ go) {
    int t = blockIdx.x;
    const float* xt = x + (size_t)t * H_;
    float pv[E_], po[E_];
#pragma unroll
    for (int e = 0; e < E_; e++) { pv[e] = 0.f; po[e] = 0.f; }
    for (int k = threadIdx.x; k < H_; k += 128) {
        float xv = xt[k];
#pragma unroll
        for (int e = 0; e < E_; e++) {
            pv[e] += xv * gv[e * H_ + k];
            po[e] += xv * go[e * H_ + k];
        }
    }
    __shared__ float red[2 * E_][128];
#pragma unroll
    for (int e = 0; e < E_; e++) {
        red[e][threadIdx.x] = pv[e];
        red[E_ + e][threadIdx.x] = po[e];
    }
    __syncthreads();
    if (threadIdx.x < 2 * E_) {
        float s = 0.f;
        for (int i = 0; i < 128; i++) s += red[threadIdx.x][i];
        red[threadIdx.x][0] = s;
    }
    __syncthreads();
    if (threadIdx.x < 2) {
        bool isO = (threadIdx.x == 1);
        float sc[E_];
#pragma unroll
        for (int e = 0; e < E_; e++) {
            float d = red[(isO ? E_ : 0) + e][0];
            sc[e] = 1.f / (1.f + expf(-d));
        }
        int e0 = 0;
        for (int e = 1; e < E_; e++) if (sc[e] > sc[e0]) e0 = e;
        int e1 = -1;
        for (int e = 0; e < E_; e++) {
            if (e == e0) continue;
            if (e1 < 0 || sc[e] > sc[e1]) e1 = e;
        }
        float t1 = expf(sc[e1] - sc[e0]);
        float w0 = 1.f / (1.f + t1);
        float w1 = t1 / (1.f + t1);
        if (!isO) {
            g_wslot_v[t * 2 + 0] = w0;
            g_wslot_v[t * 2 + 1] = w1;
            int p0 = atomicAdd(&g_cnt_v[e0], 1); g_list_v[e0 * T_ + p0] = t * 2 + 0;
            int p1 = atomicAdd(&g_cnt_v[e1], 1); g_list_v[e1 * T_ + p1] = t * 2 + 1;
        } else {
            g_wslot_o[t * 2 + 0] = w0;
            g_wslot_o[t * 2 + 1] = w1;
            int p0 = atomicAdd(&g_cnt_o[e0], 1); g_list_o[e0 * T_ + p0] = t * 2 + 0;
            int p1 = atomicAdd(&g_cnt_o[e1], 1); g_list_o[e1 * T_ + p1] = t * 2 + 1;
        }
    }
}

// ---------------- launcher ----------------
extern "C" void kernel_launch(void* const* d_in, const int* in_sizes, int n_in,
                              void* d_out, int out_size) {
    const float* x      = (const float*)d_in[0];
    const float* amask  = (const float*)d_in[1];
    const float* wq     = (const float*)d_in[2];
    const float* wk     = (const float*)d_in[3];
    const float* q_a    = (const float*)d_in[4];
    const float* q_b    = (const float*)d_in[5];
    const float* k_a    = (const float*)d_in[6];
    const float* k_b    = (const float*)d_in[7];
    const float* gv     = (const float*)d_in[8];
    const float* go     = (const float*)d_in[9];
    const float* v_base = (const float*)d_in[10];
    const float* v_a    = (const float*)d_in[11];
    const float* v_b    = (const float*)d_in[12];
    const float* o_base = (const float*)d_in[13];
    const float* o_a    = (const float*)d_in[14];
    const float* o_b    = (const float*)d_in[15];
    float* out = (float*)d_out;

#define SYM(v, s) void* v; cudaGetSymbolAddress(&v, s)
    SYM(p_L, g_L); SYM(p_xacat, g_xacat); SYM(p_xao, g_xao);
    SYM(p_wcat, g_wcat); SYM(p_wcat2, g_wcat2);
    SYM(p_list_v, g_list_v); SYM(p_list_o, g_list_o);
    SYM(p_cnt_v, g_cnt_v); SYM(p_cnt_o, g_cnt_o);
    SYM(p_ws_v, g_wslot_v); SYM(p_ws_o, g_wslot_o);
    SYM(xs_h, g_xs_h); SYM(xs_l, g_xs_l);
    SYM(qs_h, g_qs_h); SYM(qs_l, g_qs_l);
    SYM(ks_h, g_ks_h); SYM(ks_l, g_ks_l);
    SYM(cts_h, g_cts_h); SYM(cts_l, g_cts_l);
    SYM(vts_h, g_vts_h); SYM(vts_l, g_vts_l);
    SYM(Ps_h, g_Ps_h); SYM(Ps_l, g_Ps_l);
    SYM(wqs_h, g_wqs_h); SYM(wqs_l, g_wqs_l);
    SYM(wks_h, g_wks_h); SYM(wks_l, g_wks_l);
    SYM(vbs_h, g_vbs_h); SYM(vbs_l, g_vbs_l);
    SYM(obs_h, g_obs_h); SYM(obs_l, g_obs_l);
    SYM(wcs_h, g_wcs_h); SYM(wcs_l, g_wcs_l);
    SYM(wcs2_h, g_wcs2_h); SYM(wcs2_l, g_wcs2_l);
#undef SYM

    cudaFuncSetAttribute(tc_gemm<M_XA>,     cudaFuncAttributeMaxDynamicSharedMemorySize, SMEM_SZ);
    cudaFuncSetAttribute(tc_gemm<M_MOE>,    cudaFuncAttributeMaxDynamicSharedMemorySize, SMEM_SZ);
    cudaFuncSetAttribute(tc_gemm<M_QKV>,    cudaFuncAttributeMaxDynamicSharedMemorySize, SMEM_SZ);
    cudaFuncSetAttribute(tc_gemm<M_SCORES>, cudaFuncAttributeMaxDynamicSharedMemorySize, SMEM_SZ);
    cudaFuncSetAttribute(tc_gemm<M_CTX>,    cudaFuncAttributeMaxDynamicSharedMemorySize, SMEM_SZ);

    // LoRA-A weight concats (fp32)
    cudaMemcpyAsync((float*)p_wcat,           q_a, sizeof(float) * R_ * H_,      cudaMemcpyDeviceToDevice);
    cudaMemcpyAsync((float*)p_wcat + 16 * H_, k_a, sizeof(float) * R_ * H_,      cudaMemcpyDeviceToDevice);
    cudaMemcpyAsync((float*)p_wcat + 32 * H_, v_a, sizeof(float) * E_ * R_ * H_, cudaMemcpyDeviceToDevice);
    cudaMemcpyAsync((float*)p_wcat2,          o_a, sizeof(float) * E_ * R_ * H_, cudaMemcpyDeviceToDevice);

    cudaMemsetAsync(p_L, 0, sizeof(float) * (size_t)B_ * NH_ * S_);
    cudaMemsetAsync(p_xacat, 0, sizeof(float) * (size_t)T_ * 128);
    cudaMemsetAsync(p_xao, 0, sizeof(float) * (size_t)T_ * 128);
    cudaMemsetAsync(out, 0, sizeof(float) * (size_t)T_ * H_);
    init_counts_kernel<<<1, 32>>>();
    routing_kernel<<<T_, 128>>>(x, gv, go);

    // splits: inputs + weights
    split_kernel<<<1024, 256>>>((const float4*)x,      (u32*)xs_h,  (u32*)xs_l,  T_ * H_ / 4);
    split_kernel<<<1024, 256>>>((const float4*)wq,     (u32*)wqs_h, (u32*)wqs_l, H_ * H_ / 4);
    split_kernel<<<1024, 256>>>((const float4*)wk,     (u32*)wks_h, (u32*)wks_l, H_ * H_ / 4);
    split_kernel<<<2048, 256>>>((const float4*)v_base, (u32*)vbs_h, (u32*)vbs_l, E_ * H_ * H_ / 4);
    split_kernel<<<2048, 256>>>((const float4*)o_base, (u32*)obs_h, (u32*)obs_l, E_ * H_ * H_ / 4);
    split_kernel<<<256, 256>>>((const float4*)p_wcat,  (u32*)wcs_h, (u32*)wcs_l, 128 * H_ / 4);
    split_kernel<<<256, 256>>>((const float4*)p_wcat2, (u32*)wcs2_h, (u32*)wcs2_l, 128 * H_ / 4);

    // XA: xacat = x @ wcat^T (fp32 out, K-split x4, atomic accumulate)
    tc_gemm<M_XA><<<dim3(4, T_ / 128), 256, SMEM_SZ>>>(
        (cbf*)xs_h, (cbf*)xs_l, (cbf*)wcs_h, (cbf*)wcs_l,
        (float*)p_xacat, nullptr, nullptr, nullptr, nullptr, nullptr, nullptr, nullptr,
        nullptr, nullptr);

    // fused Q-proj (z=0), K-proj (z=1), V-MoE (z=2..7, non-atomic slot stores)
    tc_gemm<M_QKV><<<dim3(H_ / 128, T_ / 128, 2 + E_), 256, SMEM_SZ>>>(
        nullptr, nullptr, nullptr, nullptr,
        nullptr, nullptr, nullptr,
        nullptr, q_b,
        (const int*)p_list_v, (const int*)p_cnt_v, (const float*)p_ws_v,
        k_b, v_b);

    // slot-sum + transpose + split V -> vts planes
    tsplit_kernel<<<dim3(H_ / 32, S_ / 32, B_), 256>>>();

    // attention: scores with fused exp + row-sum epilogue, then ctx with 1/L epilogue
    tc_gemm<M_SCORES><<<dim3(S_ / 128, S_ / 128, B_ * NH_), 256, SMEM_SZ>>>(
        (cbf*)qs_h, (cbf*)qs_l, (cbf*)ks_h, (cbf*)ks_l,
        nullptr, nullptr, nullptr, nullptr, nullptr, nullptr, nullptr, amask,
        nullptr, nullptr);
    tc_gemm<M_CTX><<<dim3(1, S_ / 128, B_ * NH_), 256, SMEM_SZ>>>(
        (cbf*)Ps_h, (cbf*)Ps_l, (cbf*)vts_h, (cbf*)vts_l,
        nullptr, (u32*)cts_h, (u32*)cts_l, nullptr, nullptr, nullptr, nullptr, nullptr,
        nullptr, nullptr);

    // O path
    tc_gemm<M_XA><<<dim3(4, T_ / 128), 256, SMEM_SZ>>>(
        (cbf*)cts_h, (cbf*)cts_l, (cbf*)wcs2_h, (cbf*)wcs2_l,
        (float*)p_xao, nullptr, nullptr, nullptr, nullptr, nullptr, nullptr, nullptr,
        nullptr, nullptr);
    tc_gemm<M_MOE><<<dim3(H_ / 128, T_ / 128, E_), 256, SMEM_SZ>>>(
        (cbf*)cts_h, (cbf*)cts_l, (cbf*)obs_h, (cbf*)obs_l,
        out, nullptr, nullptr, (const float*)p_xao, o_b,
        (const int*)p_list_o, (const int*)p_cnt_o, (const float*)p_ws_o,
        nullptr, nullptr);
}

// round 17
// speedup vs baseline: 1.1178x; 1.0300x over previous
#include <cuda_runtime.h>
#include <cuda_bf16.h>
#include <math.h>

typedef unsigned int u32;
typedef unsigned long long u64;

// ---------------- problem constants ----------------
#define B_   2
#define S_   2048
#define H_   2048
#define NH_  16
#define DH_  128
#define E_   6
#define R_   16
#define T_   (B_ * S_)            // 4096 tokens
#define SCALING_ 8.0f
#define INV_SQRT_DH 0.08838834764831845f

// tile: 128 rows x 32 bf16 = 64B/row, XOR-swizzled. 8KB per plane.
#define PLB 8192
#define STG_B (4 * PLB)           // Ahi, Alo, Bhi, Blo = 32KB
#define NSTG 3
#define SMEM_SZ (NSTG * STG_B)    // 96KB

// ---------------- scratch: fp32 ----------------
__device__ float g_vslot[2 * T_ * H_]; // per-slot rows [en][n]; reused for V then O
__device__ float g_L[B_ * NH_ * S_];   // unnormalized softmax row sums
__device__ float g_xacat[T_ * 128];
__device__ float g_xao[T_ * 128];
__device__ float g_wcat[128 * H_];
__device__ float g_wcat2[128 * H_];
__device__ int   g_list_v[E_ * T_];
__device__ int   g_list_o[E_ * T_];
__device__ int   g_cnt_v[E_];
__device__ int   g_cnt_o[E_];
__device__ float g_wslot_v[T_ * 2];
__device__ float g_wslot_o[T_ * 2];

// ---------------- scratch: bf16 hi/lo planes (u32 = 2 bf16) ----------------
#define PT (T_ * H_ / 2)
#define PW (H_ * H_ / 2)
#define PE (E_ * H_ * H_ / 2)
#define PC (128 * H_ / 2)
__device__ u32 g_xs_h[PT],  g_xs_l[PT];
__device__ u32 g_qs_h[PT],  g_qs_l[PT];
__device__ u32 g_ks_h[PT],  g_ks_l[PT];
__device__ u32 g_cts_h[PT], g_cts_l[PT];
__device__ u32 g_vts_h[PT], g_vts_l[PT];   // V transposed planes [b*H+n][S]
__device__ u32 g_Ps_h[(size_t)B_ * NH_ * S_ * S_ / 2];
__device__ u32 g_Ps_l[(size_t)B_ * NH_ * S_ * S_ / 2];
__device__ u32 g_wqs_h[PW], g_wqs_l[PW];
__device__ u32 g_wks_h[PW], g_wks_l[PW];
__device__ u32 g_vbs_h[PE], g_vbs_l[PE];
__device__ u32 g_obs_h[PE], g_obs_l[PE];
__device__ u32 g_wcs_h[PC], g_wcs_l[PC];
__device__ u32 g_wcs2_h[PC], g_wcs2_l[PC];

// ---------------- helpers ----------------
__device__ __forceinline__ u32 s2u(const void* p) {
    u32 a;
    asm("{ .reg .u64 t; cvta.to.shared.u64 t, %1; cvt.u32.u64 %0, t; }" : "=r"(a) : "l"(p));
    return a;
}
__device__ __forceinline__ u32 pack_bf2(float a, float b) {
    __nv_bfloat162 t = __floats2bfloat162_rn(a, b);
    return *reinterpret_cast<u32*>(&t);
}
__device__ __forceinline__ void split4(float4 v, u32& h0, u32& h1, u32& l0, u32& l1) {
    __nv_bfloat162 p0 = __floats2bfloat162_rn(v.x, v.y);
    __nv_bfloat162 p1 = __floats2bfloat162_rn(v.z, v.w);
    h0 = *reinterpret_cast<u32*>(&p0);
    h1 = *reinterpret_cast<u32*>(&p1);
    l0 = pack_bf2(v.x - __low2float(p0), v.y - __high2float(p0));
    l1 = pack_bf2(v.z - __low2float(p1), v.w - __high2float(p1));
}
__device__ __forceinline__ void split2(float a, float b, u32& h, u32& l) {
    __nv_bfloat162 p = __floats2bfloat162_rn(a, b);
    h = *reinterpret_cast<u32*>(&p);
    l = pack_bf2(a - __low2float(p), b - __high2float(p));
}
__device__ __forceinline__ void mma_bf16(float* c, u32 a0, u32 a1, u32 a2, u32 a3, u32 b0, u32 b1) {
    asm volatile(
        "mma.sync.aligned.m16n8k16.row.col.f32.bf16.bf16.f32 "
        "{%0,%1,%2,%3}, {%4,%5,%6,%7}, {%8,%9}, {%0,%1,%2,%3};"
        : "+f"(c[0]), "+f"(c[1]), "+f"(c[2]), "+f"(c[3])
        : "r"(a0), "r"(a1), "r"(a2), "r"(a3), "r"(b0), "r"(b1));
}
__device__ __forceinline__ void ldsm4(u32* r, u32 a) {
    asm volatile("ldmatrix.sync.aligned.m8n8.x4.shared.b16 {%0,%1,%2,%3}, [%4];"
        : "=r"(r[0]), "=r"(r[1]), "=r"(r[2]), "=r"(r[3]) : "r"(a));
}
__device__ __forceinline__ void cpa16(u32 dst, const void* src) {
    asm volatile("cp.async.ca.shared.global [%0], [%1], 16;" :: "r"(dst), "l"(src));
}
#define CPA_COMMIT() asm volatile("cp.async.commit_group;" ::: "memory")
#define CPA_WAIT1()  asm volatile("cp.async.wait_group 1;" ::: "memory")
#define CPA_WAIT0()  asm volatile("cp.async.wait_group 0;" ::: "memory")
// XOR swizzle: row 64B, seg = 16B chunk idx (0..3)
__device__ __forceinline__ u32 swb(int row, int seg) {
    return (u32)(row * 64 + ((seg ^ ((row >> 1) & 3)) * 16));
}

// one k16 MMA step over 128x128 tile (3-term bf16 split), stage base = stg
__device__ __forceinline__ void compute_k16(u32 stg, int ks, int wm, int wn, int lane,
                                            float (&acc)[4][4][4]) {
    int j = lane >> 3, r7 = lane & 7;
    int rowA = wm * 64 + (j & 1) * 8 + r7;
    int segA = ks * 2 + (j >> 1);
    u32 aH = stg + swb(rowA, segA);
    u32 aL = aH + PLB;
    int rowB = wn * 32 + (j >> 1) * 8 + r7;
    int segB = ks * 2 + (j & 1);
    u32 bH = stg + 2 * PLB + swb(rowB, segB);
    u32 bL = bH + PLB;

    u32 bh[2][4], bl[2][4], am[4][4];
    ldsm4(bh[0], bH); ldsm4(bh[1], bH + 1024);
    ldsm4(bl[0], bL); ldsm4(bl[1], bL + 1024);
#pragma unroll
    for (int mf = 0; mf < 4; mf++) ldsm4(am[mf], aH + mf * 1024);
#pragma unroll
    for (int mf = 0; mf < 4; mf++)
#pragma unroll
        for (int nf = 0; nf < 4; nf++) {
            const u32* b = &bh[nf >> 1][(nf & 1) * 2];
            mma_bf16(acc[mf][nf], am[mf][0], am[mf][1], am[mf][2], am[mf][3], b[0], b[1]);
        }
#pragma unroll
    for (int mf = 0; mf < 4; mf++)
#pragma unroll
        for (int nf = 0; nf < 4; nf++) {
            const u32* b = &bl[nf >> 1][(nf & 1) * 2];
            mma_bf16(acc[mf][nf], am[mf][0], am[mf][1], am[mf][2], am[mf][3], b[0], b[1]);
        }
#pragma unroll
    for (int mf = 0; mf < 4; mf++) ldsm4(am[mf], aL + mf * 1024);
#pragma unroll
    for (int mf = 0; mf < 4; mf++)
#pragma unroll
        for (int nf = 0; nf < 4; nf++) {
            const u32* b = &bh[nf >> 1][(nf & 1) * 2];
            mma_bf16(acc[mf][nf], am[mf][0], am[mf][1], am[mf][2], am[mf][3], b[0], b[1]);
        }
}

// ---------------- the one NT GEMM kernel ----------------
enum { M_XA = 1, M_MOE = 2, M_SCORES = 4, M_CTX = 5, M_QKV = 6 };

typedef const __nv_bfloat16 cbf;

template <int MODE>
__global__ void __launch_bounds__(256) tc_gemm(
    cbf* Ah_, cbf* Al_, cbf* Bh_, cbf* Bl_,
    float* __restrict__ Cf, u32* __restrict__ Ch, u32* __restrict__ Cl,
    const float* __restrict__ Lab, const float* __restrict__ Lbb,
    const int* __restrict__ glist, const int* __restrict__ gcnt,
    const float* __restrict__ gw,
    const float* __restrict__ Lb2, const float* __restrict__ Lb3) {
    constexpr bool GATHER = (MODE == M_MOE);
    constexpr bool QKV = (MODE == M_QKV);
    constexpr bool LORA = (MODE == M_MOE || MODE == M_QKV);
    constexpr bool USETOK = (GATHER || QKV);
    extern __shared__ __align__(16) unsigned char dsm[];
    __shared__ int esm[128];
    __shared__ int tok[128];
    __shared__ float s_row[128];

    int tid = threadIdx.x;
    int m0 = blockIdx.y * 128, n0 = blockIdx.x * 128, z = blockIdx.z;

    cbf *pAh, *pAl, *pBh, *pBl;
    const float* La = nullptr;
    const float* Lb = nullptr;
    long lda, ldb, ldc = 0;
    int K, ldla = 0;
    size_t coff = 0;

    if constexpr (MODE == M_XA) {
        // K-split along blockIdx.x: 4 chunks of 512
        int kxo = blockIdx.x * 512;
        pAh = Ah_ + (size_t)m0 * H_ + kxo; pAl = Al_ + (size_t)m0 * H_ + kxo;
        pBh = Bh_ + kxo; pBl = Bl_ + kxo;
        coff = (size_t)m0 * 128;
        lda = ldb = H_; ldc = 128; K = 512;
    } else if constexpr (MODE == M_MOE) {
        pAh = Ah_; pAl = Al_;
        pBh = Bh_ + (size_t)z * H_ * H_ + (size_t)n0 * H_;
        pBl = Bl_ + (size_t)z * H_ * H_ + (size_t)n0 * H_;
        lda = ldb = H_; K = H_;
        La = Lab + z * R_; ldla = 128;
        Lb = Lbb + (size_t)z * H_ * R_ + (size_t)n0 * R_;
    } else if constexpr (MODE == M_QKV) {
        pAh = (cbf*)g_xs_h; pAl = (cbf*)g_xs_l;
        size_t bo = (size_t)n0 * H_;
        if (z == 0)      { pBh = (cbf*)g_wqs_h + bo; pBl = (cbf*)g_wqs_l + bo; }
        else if (z == 1) { pBh = (cbf*)g_wks_h + bo; pBl = (cbf*)g_wks_l + bo; }
        else {
            size_t eo = (size_t)(z - 2) * H_ * H_;
            pBh = (cbf*)g_vbs_h + eo + bo; pBl = (cbf*)g_vbs_l + eo + bo;
        }
        lda = ldb = H_; K = H_; ldla = 128;
        La = g_xacat + (z == 0 ? 0 : (z == 1 ? 16 : 32 + (z - 2) * R_));
        Lb = (z == 0 ? Lbb : (z == 1 ? Lb2 : Lb3 + (size_t)(z - 2) * H_ * R_)) + (size_t)n0 * R_;
    } else if constexpr (MODE == M_SCORES) {
        int b = z >> 4, h = z & 15;
        size_t ao = ((size_t)b * S_ + m0) * H_ + h * DH_;
        size_t bo = ((size_t)b * S_ + n0) * H_ + h * DH_;
        pAh = Ah_ + ao; pAl = Al_ + ao;
        pBh = Bh_ + bo; pBl = Bl_ + bo;
        coff = (size_t)z * S_ * S_ + (size_t)m0 * S_ + n0;
        lda = ldb = H_; ldc = S_; K = DH_;
    } else {  // M_CTX
        size_t ao = (size_t)z * S_ * S_ + (size_t)m0 * S_;
        size_t bo = (size_t)z * DH_ * S_;
        pAh = Ah_ + ao; pAl = Al_ + ao;
        pBh = Bh_ + bo; pBl = Bl_ + bo;
        int b = z >> 4, h = z & 15;
        coff = ((size_t)b * S_ + m0) * H_ + h * DH_;
        lda = S_; ldb = S_; ldc = H_; K = S_;
    }

    if constexpr (MODE == M_QKV) {
        if (z >= 2 && m0 >= gcnt[z - 2]) return;
        if (tid < 128) {
            if (z < 2) { tok[tid] = m0 + tid; esm[tid] = 0; }
            else {
                int count = gcnt[z - 2];
                int idx = m0 + tid;
                int en = (idx < count) ? glist[(z - 2) * T_ + idx] : -1;
                esm[tid] = en;
                tok[tid] = (en >= 0) ? (en >> 1) : 0;
            }
        }
        __syncthreads();
    } else if constexpr (GATHER) {
        int count = gcnt[z];
        if (m0 >= count) return;
        if (tid < 128) {
            int idx = m0 + tid;
            int en = (idx < count) ? glist[z * T_ + idx] : -1;
            esm[tid] = en;
            tok[tid] = (en >= 0) ? (en >> 1) : 0;
        }
        __syncthreads();
    }
    if constexpr (MODE == M_SCORES) {
        if (tid < 128) s_row[tid] = (1.0f - gw[(size_t)(z >> 4) * S_ + n0 + tid]) * (-10000.0f);
    }
    if constexpr (MODE == M_CTX) {
        if (tid < 128) s_row[tid] = 1.0f / g_L[(size_t)z * S_ + m0 + tid];
    }

    int wid = tid >> 5, lane = tid & 31;
    int wm = wid & 1, wn = wid >> 1, g = lane >> 2, tig = lane & 3;
    u32 smb = s2u(dsm);

    // per-thread loader pointers: rows cr and cr+64, seg = tid&3
    int cr = tid >> 2, seg = tid & 3;
    int ra0 = cr, ra1 = cr + 64;
    long ga0 = USETOK ? (long)tok[ra0] : ra0;
    long ga1 = USETOK ? (long)tok[ra1] : ra1;
    cbf* sAh0 = pAh + ga0 * lda + seg * 8;
    cbf* sAh1 = pAh + ga1 * lda + seg * 8;
    cbf* sAl0 = pAl + ga0 * lda + seg * 8;
    cbf* sAl1 = pAl + ga1 * lda + seg * 8;
    cbf* sBh0 = pBh + (long)ra0 * ldb + seg * 8;
    cbf* sBh1 = pBh + (long)ra1 * ldb + seg * 8;
    cbf* sBl0 = pBl + (long)ra0 * ldb + seg * 8;
    cbf* sBl1 = pBl + (long)ra1 * ldb + seg * 8;
    u32 d0 = swb(ra0, seg), d1 = swb(ra1, seg);

#define LOAD_STAGE(s, ktE) do { u32 st_ = smb + (s) * STG_B; int k_ = (ktE); \
    cpa16(st_ + d0, sAh0 + k_);            cpa16(st_ + d1, sAh1 + k_); \
    cpa16(st_ + PLB + d0, sAl0 + k_);      cpa16(st_ + PLB + d1, sAl1 + k_); \
    cpa16(st_ + 2 * PLB + d0, sBh0 + k_);  cpa16(st_ + 2 * PLB + d1, sBh1 + k_); \
    cpa16(st_ + 3 * PLB + d0, sBl0 + k_);  cpa16(st_ + 3 * PLB + d1, sBl1 + k_); } while (0)

    float acc[4][4][4];
#pragma unroll
    for (int a = 0; a < 4; a++)
#pragma unroll
        for (int b = 0; b < 4; b++)
#pragma unroll
            for (int c = 0; c < 4; c++) acc[a][b][c] = 0.f;

    int nk = K / 32;
    LOAD_STAGE(0, 0);  CPA_COMMIT();
    LOAD_STAGE(1, 32); CPA_COMMIT();

    for (int it = 0; it < nk; it++) {
        CPA_WAIT1();
        __syncthreads();
        // R8 schedule: compute FIRST, then prefetch
        u32 stg = smb + (it % NSTG) * STG_B;
        compute_k16(stg, 0, wm, wn, lane, acc);
        compute_k16(stg, 1, wm, wn, lane, acc);
        if (it + 2 < nk) LOAD_STAGE((it + 2) % NSTG, (it + 2) * 32);
        CPA_COMMIT();
    }
    CPA_WAIT0();
    __syncthreads();

    if constexpr (LORA) {
        // one extra k16: A = SCALING*La (fp32, rows via tok), B = Lb (fp32); segs 0..1
#pragma unroll
        for (int i = 0; i < 2; i++) {
            int f = tid + i * 256;
            int row = f >> 2, kc = (f & 3) * 4;
            size_t ro = (size_t)tok[row] * ldla;
            float4 v = *(const float4*)(La + ro + kc);
            v.x *= SCALING_; v.y *= SCALING_; v.z *= SCALING_; v.w *= SCALING_;
            u32 h0, h1, l0, l1;
            split4(v, h0, h1, l0, l1);
            u32 off = smb + swb(row, kc >> 3) + (kc & 7) * 2;
            asm volatile("st.shared.v2.u32 [%0], {%1,%2};" :: "r"(off), "r"(h0), "r"(h1));
            asm volatile("st.shared.v2.u32 [%0], {%1,%2};" :: "r"(off + PLB), "r"(l0), "r"(l1));
            float4 u = *(const float4*)(Lb + (size_t)row * R_ + kc);
            split4(u, h0, h1, l0, l1);
            asm volatile("st.shared.v2.u32 [%0], {%1,%2};" :: "r"(off + 2 * PLB), "r"(h0), "r"(h1));
            asm volatile("st.shared.v2.u32 [%0], {%1,%2};" :: "r"(off + 3 * PLB), "r"(l0), "r"(l1));
        }
        __syncthreads();
        compute_k16(smb, 0, wm, wn, lane, acc);
    }

    // ---------------- epilogues ----------------
    if constexpr (MODE == M_QKV) {
        if (z < 2) {
            u32* ch = (z == 0) ? g_qs_h : g_ks_h;
            u32* cl = (z == 0) ? g_qs_l : g_ks_l;
            size_t co = (size_t)m0 * H_ + n0;
#pragma unroll
            for (int mf = 0; mf < 4; mf++) {
#pragma unroll
                for (int half = 0; half < 2; half++) {
                    int m = wm * 64 + mf * 16 + g + half * 8;
#pragma unroll
                    for (int nf = 0; nf < 4; nf++) {
                        int n = wn * 32 + nf * 8 + tig * 2;
                        u32 h, l;
                        split2(acc[mf][nf][half * 2 + 0], acc[mf][nf][half * 2 + 1], h, l);
                        size_t ix = (co + (size_t)m * H_ + n) >> 1;
                        ch[ix] = h;
                        cl[ix] = l;
                    }
                }
            }
        } else {
            // V MoE: non-atomic per-slot stores (each slot row written exactly once)
#pragma unroll
            for (int mf = 0; mf < 4; mf++) {
#pragma unroll
                for (int half = 0; half < 2; half++) {
                    int lr = wm * 64 + mf * 16 + g + half * 8;
                    int en = esm[lr];
                    if (en < 0) continue;
                    float w = gw[en];
                    float* p = g_vslot + (size_t)en * H_ + n0;
#pragma unroll
                    for (int nf = 0; nf < 4; nf++) {
                        int n = wn * 32 + nf * 8 + tig * 2;
                        float2 v = {w * acc[mf][nf][half * 2 + 0], w * acc[mf][nf][half * 2 + 1]};
                        *(float2*)(p + n) = v;
                    }
                }
            }
        }
    } else if constexpr (GATHER) {
        // O MoE: non-atomic per-slot stores into g_vslot (reused; combined later)
#pragma unroll
        for (int mf = 0; mf < 4; mf++) {
#pragma unroll
            for (int half = 0; half < 2; half++) {
                int lr = wm * 64 + mf * 16 + g + half * 8;
                int en = esm[lr];
                if (en < 0) continue;
                float w = gw[en];
                float* p = g_vslot + (size_t)en * H_ + n0;
#pragma unroll
                for (int nf = 0; nf < 4; nf++) {
                    int n = wn * 32 + nf * 8 + tig * 2;
                    float2 v = {w * acc[mf][nf][half * 2 + 0], w * acc[mf][nf][half * 2 + 1]};
                    *(float2*)(p + n) = v;
                }
            }
        }
    } else if constexpr (MODE == M_SCORES) {
        // exp epilogue: write unnormalized exp(P) planes + atomic row sums
#pragma unroll
        for (int mf = 0; mf < 4; mf++) {
#pragma unroll
            for (int half = 0; half < 2; half++) {
                int r = wm * 64 + mf * 16 + g + half * 8;
                float rs = 0.f;
#pragma unroll
                for (int nf = 0; nf < 4; nf++) {
                    int cn = wn * 32 + nf * 8 + tig * 2;
                    float e0 = __expf(acc[mf][nf][half * 2 + 0] * INV_SQRT_DH + s_row[cn]);
                    float e1 = __expf(acc[mf][nf][half * 2 + 1] * INV_SQRT_DH + s_row[cn + 1]);
                    rs += e0 + e1;
                    u32 h, l;
                    split2(e0, e1, h, l);
                    size_t ix = (coff + (size_t)r * S_ + cn) >> 1;
                    g_Ps_h[ix] = h;
                    g_Ps_l[ix] = l;
                }
                rs += __shfl_xor_sync(0xffffffffu, rs, 1);
                rs += __shfl_xor_sync(0xffffffffu, rs, 2);
                if (tig == 0) atomicAdd(&g_L[(size_t)z * S_ + m0 + r], rs);
            }
        }
    } else if constexpr (MODE == M_CTX) {
#pragma unroll
        for (int mf = 0; mf < 4; mf++) {
#pragma unroll
            for (int half = 0; half < 2; half++) {
                int m = wm * 64 + mf * 16 + g + half * 8;
                float iv = s_row[m];
#pragma unroll
                for (int nf = 0; nf < 4; nf++) {
                    int n = wn * 32 + nf * 8 + tig * 2;
                    u32 h, l;
                    split2(acc[mf][nf][half * 2 + 0] * iv, acc[mf][nf][half * 2 + 1] * iv, h, l);
                    size_t ix = (coff + (size_t)m * ldc + n) >> 1;
                    Ch[ix] = h;
                    Cl[ix] = l;
                }
            }
        }
    } else {  // M_XA: fp32 atomic accumulate (K-split partials)
        float* C = Cf + coff;
#pragma unroll
        for (int mf = 0; mf < 4; mf++) {
#pragma unroll
            for (int half = 0; half < 2; half++) {
                int m = wm * 64 + mf * 16 + g + half * 8;
#pragma unroll
                for (int nf = 0; nf < 4; nf++) {
                    int n = wn * 32 + nf * 8 + tig * 2;
                    atomicAdd(C + (size_t)m * ldc + n, acc[mf][nf][half * 2 + 0]);
                    atomicAdd(C + (size_t)m * ldc + n + 1, acc[mf][nf][half * 2 + 1]);
                }
            }
        }
    }
#undef LOAD_STAGE
}

// ---------------- transpose + split: g_vslot [2 rows per t] -> vts planes [b*H+n][S] ----------------
__global__ void tsplit_kernel() {
    __shared__ float tile[32][33];
    int bx = blockIdx.x, by = blockIdx.y, bz = blockIdx.z;
    int tx = threadIdx.x & 31, ty = threadIdx.x >> 5;
#pragma unroll
    for (int r = 0; r < 32; r += 8) {
        size_t t = (size_t)(bz * S_ + by * 32 + r + ty);
        int col = bx * 32 + tx;
        tile[r + ty][tx] = g_vslot[(2 * t) * H_ + col] + g_vslot[(2 * t + 1) * H_ + col];
    }
    __syncthreads();
#pragma unroll
    for (int r = 0; r < 32; r += 8) {
        int n = r + ty;
        if (tx < 16) {
            float a = tile[2 * tx][n], b = tile[2 * tx + 1][n];
            u32 h, l;
            split2(a, b, h, l);
            size_t ix = (((size_t)(bz * H_ + bx * 32 + n)) * S_ + by * 32) / 2 + tx;
            g_vts_h[ix] = h;
            g_vts_l[ix] = l;
        }
    }
}

// ---------------- combine: out[t][n] = slot[2t][n] + slot[2t+1][n] ----------------
__global__ void combine_kernel(float* __restrict__ out) {
    int i4 = blockIdx.x * blockDim.x + threadIdx.x;      // float4 index
    if (i4 >= T_ * H_ / 4) return;
    size_t i = (size_t)i4 * 4;
    size_t t = i / H_, n = i % H_;
    const float4 a = *(const float4*)&g_vslot[(2 * t) * H_ + n];
    const float4 b = *(const float4*)&g_vslot[(2 * t + 1) * H_ + n];
    float4 r = {a.x + b.x, a.y + b.y, a.z + b.z, a.w + b.w};
    *(float4*)&out[i] = r;
}

// ---------------- split fp32 -> bf16 hi/lo planes (MLP=4 batched) ----------------
__global__ void split_kernel(const float4* __restrict__ src, u32* __restrict__ hi,
                             u32* __restrict__ lo, int n4) {
    int stride = gridDim.x * blockDim.x;
    for (int i = blockIdx.x * blockDim.x + threadIdx.x; i < n4; i += 4 * stride) {
        float4 v[4];
#pragma unroll
        for (int j = 0; j < 4; j++) {
            int idx = i + j * stride;
            if (idx < n4) v[j] = src[idx];
        }
#pragma unroll
        for (int j = 0; j < 4; j++) {
            int idx = i + j * stride;
            if (idx < n4) {
                u32 h0, h1, l0, l1;
                split4(v[j], h0, h1, l0, l1);
                *(uint2*)&hi[(size_t)idx * 2] = make_uint2(h0, h1);
                *(uint2*)&lo[(size_t)idx * 2] = make_uint2(l0, l1);
            }
        }
    }
}

// ---------------- init counts ----------------
__global__ void init_counts_kernel() {
    if (threadIdx.x < E_) {
        g_cnt_v[threadIdx.x] = 0;
        g_cnt_o[threadIdx.x] = 0;
    }
}

// ---------------- routing ----------------
__global__ void routing_kernel(const float* __restrict__ x,
                               const float* __restrict__ gv,
                               const float* __restrict__ go) {
    int t = blockIdx.x;
    const float* xt = x + (size_t)t * H_;
    float pv[E_], po[E_];
#pragma unroll
    for (int e = 0; e < E_; e++) { pv[e] = 0.f; po[e] = 0.f; }
    for (int k = threadIdx.x; k < H_; k += 128) {
        float xv = xt[k];
#pragma unroll
        for (int e = 0; e < E_; e++) {
            pv[e] += xv * gv[e * H_ + k];
            po[e] += xv * go[e * H_ + k];
        }
    }
    __shared__ float red[2 * E_][128];
#pragma unroll
    for (int e = 0; e < E_; e++) {
        red[e][threadIdx.x] = pv[e];
        red[E_ + e][threadIdx.x] = po[e];
    }
    __syncthreads();
    if (threadIdx.x < 2 * E_) {
        float s = 0.f;
        for (int i = 0; i < 128; i++) s += red[threadIdx.x][i];
        red[threadIdx.x][0] = s;
    }
    __syncthreads();
    if (threadIdx.x < 2) {
        bool isO = (threadIdx.x == 1);
        float sc[E_];
#pragma unroll
        for (int e = 0; e < E_; e++) {
            float d = red[(isO ? E_ : 0) + e][0];
            sc[e] = 1.f / (1.f + expf(-d));
        }
        int e0 = 0;
        for (int e = 1; e < E_; e++) if (sc[e] > sc[e0]) e0 = e;
        int e1 = -1;
        for (int e = 0; e < E_; e++) {
            if (e == e0) continue;
            if (e1 < 0 || sc[e] > sc[e1]) e1 = e;
        }
        float t1 = expf(sc[e1] - sc[e0]);
        float w0 = 1.f / (1.f + t1);
        float w1 = t1 / (1.f + t1);
        if (!isO) {
            g_wslot_v[t * 2 + 0] = w0;
            g_wslot_v[t * 2 + 1] = w1;
            int p0 = atomicAdd(&g_cnt_v[e0], 1); g_list_v[e0 * T_ + p0] = t * 2 + 0;
            int p1 = atomicAdd(&g_cnt_v[e1], 1); g_list_v[e1 * T_ + p1] = t * 2 + 1;
        } else {
            g_wslot_o[t * 2 + 0] = w0;
            g_wslot_o[t * 2 + 1] = w1;
            int p0 = atomicAdd(&g_cnt_o[e0], 1); g_list_o[e0 * T_ + p0] = t * 2 + 0;
            int p1 = atomicAdd(&g_cnt_o[e1], 1); g_list_o[e1 * T_ + p1] = t * 2 + 1;
        }
    }
}

// ---------------- launcher ----------------
extern "C" void kernel_launch(void* const* d_in, const int* in_sizes, int n_in,
                              void* d_out, int out_size) {
    const float* x      = (const float*)d_in[0];
    const float* amask  = (const float*)d_in[1];
    const float* wq     = (const float*)d_in[2];
    const float* wk     = (const float*)d_in[3];
    const float* q_a    = (const float*)d_in[4];
    const float* q_b    = (const float*)d_in[5];
    const float* k_a    = (const float*)d_in[6];
    const float* k_b    = (const float*)d_in[7];
    const float* gv     = (const float*)d_in[8];
    const float* go     = (const float*)d_in[9];
    const float* v_base = (const float*)d_in[10];
    const float* v_a    = (const float*)d_in[11];
    const float* v_b    = (const float*)d_in[12];
    const float* o_base = (const float*)d_in[13];
    const float* o_a    = (const float*)d_in[14];
    const float* o_b    = (const float*)d_in[15];
    float* out = (float*)d_out;

#define SYM(v, s) void* v; cudaGetSymbolAddress(&v, s)
    SYM(p_L, g_L); SYM(p_xacat, g_xacat); SYM(p_xao, g_xao);
    SYM(p_wcat, g_wcat); SYM(p_wcat2, g_wcat2);
    SYM(p_list_v, g_list_v); SYM(p_list_o, g_list_o);
    SYM(p_cnt_v, g_cnt_v); SYM(p_cnt_o, g_cnt_o);
    SYM(p_ws_v, g_wslot_v); SYM(p_ws_o, g_wslot_o);
    SYM(xs_h, g_xs_h); SYM(xs_l, g_xs_l);
    SYM(qs_h, g_qs_h); SYM(qs_l, g_qs_l);
    SYM(ks_h, g_ks_h); SYM(ks_l, g_ks_l);
    SYM(cts_h, g_cts_h); SYM(cts_l, g_cts_l);
    SYM(vts_h, g_vts_h); SYM(vts_l, g_vts_l);
    SYM(Ps_h, g_Ps_h); SYM(Ps_l, g_Ps_l);
    SYM(wqs_h, g_wqs_h); SYM(wqs_l, g_wqs_l);
    SYM(wks_h, g_wks_h); SYM(wks_l, g_wks_l);
    SYM(vbs_h, g_vbs_h); SYM(vbs_l, g_vbs_l);
    SYM(obs_h, g_obs_h); SYM(obs_l, g_obs_l);
    SYM(wcs_h, g_wcs_h); SYM(wcs_l, g_wcs_l);
    SYM(wcs2_h, g_wcs2_h); SYM(wcs2_l, g_wcs2_l);
#undef SYM

    cudaFuncSetAttribute(tc_gemm<M_XA>,     cudaFuncAttributeMaxDynamicSharedMemorySize, SMEM_SZ);
    cudaFuncSetAttribute(tc_gemm<M_MOE>,    cudaFuncAttributeMaxDynamicSharedMemorySize, SMEM_SZ);
    cudaFuncSetAttribute(tc_gemm<M_QKV>,    cudaFuncAttributeMaxDynamicSharedMemorySize, SMEM_SZ);
    cudaFuncSetAttribute(tc_gemm<M_SCORES>, cudaFuncAttributeMaxDynamicSharedMemorySize, SMEM_SZ);
    cudaFuncSetAttribute(tc_gemm<M_CTX>,    cudaFuncAttributeMaxDynamicSharedMemorySize, SMEM_SZ);

    // LoRA-A weight concats (fp32)
    cudaMemcpyAsync((float*)p_wcat,           q_a, sizeof(float) * R_ * H_,      cudaMemcpyDeviceToDevice);
    cudaMemcpyAsync((float*)p_wcat + 16 * H_, k_a, sizeof(float) * R_ * H_,      cudaMemcpyDeviceToDevice);
    cudaMemcpyAsync((float*)p_wcat + 32 * H_, v_a, sizeof(float) * E_ * R_ * H_, cudaMemcpyDeviceToDevice);
    cudaMemcpyAsync((float*)p_wcat2,          o_a, sizeof(float) * E_ * R_ * H_, cudaMemcpyDeviceToDevice);

    cudaMemsetAsync(p_L, 0, sizeof(float) * (size_t)B_ * NH_ * S_);
    cudaMemsetAsync(p_xacat, 0, sizeof(float) * (size_t)T_ * 128);
    cudaMemsetAsync(p_xao, 0, sizeof(float) * (size_t)T_ * 128);
    init_counts_kernel<<<1, 32>>>();
    routing_kernel<<<T_, 128>>>(x, gv, go);

    // splits: inputs + weights
    split_kernel<<<1024, 256>>>((const float4*)x,      (u32*)xs_h,  (u32*)xs_l,  T_ * H_ / 4);
    split_kernel<<<1024, 256>>>((const float4*)wq,     (u32*)wqs_h, (u32*)wqs_l, H_ * H_ / 4);
    split_kernel<<<1024, 256>>>((const float4*)wk,     (u32*)wks_h, (u32*)wks_l, H_ * H_ / 4);
    split_kernel<<<2048, 256>>>((const float4*)v_base, (u32*)vbs_h, (u32*)vbs_l, E_ * H_ * H_ / 4);
    split_kernel<<<2048, 256>>>((const float4*)o_base, (u32*)obs_h, (u32*)obs_l, E_ * H_ * H_ / 4);
    split_kernel<<<256, 256>>>((const float4*)p_wcat,  (u32*)wcs_h, (u32*)wcs_l, 128 * H_ / 4);
    split_kernel<<<256, 256>>>((const float4*)p_wcat2, (u32*)wcs2_h, (u32*)wcs2_l, 128 * H_ / 4);

    // XA: xacat = x @ wcat^T (fp32 out, K-split x4, atomic accumulate)
    tc_gemm<M_XA><<<dim3(4, T_ / 128), 256, SMEM_SZ>>>(
        (cbf*)xs_h, (cbf*)xs_l, (cbf*)wcs_h, (cbf*)wcs_l,
        (float*)p_xacat, nullptr, nullptr, nullptr, nullptr, nullptr, nullptr, nullptr,
        nullptr, nullptr);

    // fused Q-proj (z=0), K-proj (z=1), V-MoE (z=2..7, non-atomic slot stores)
    tc_gemm<M_QKV><<<dim3(H_ / 128, T_ / 128, 2 + E_), 256, SMEM_SZ>>>(
        nullptr, nullptr, nullptr, nullptr,
        nullptr, nullptr, nullptr,
        nullptr, q_b,
        (const int*)p_list_v, (const int*)p_cnt_v, (const float*)p_ws_v,
        k_b, v_b);

    // slot-sum + transpose + split V -> vts planes
    tsplit_kernel<<<dim3(H_ / 32, S_ / 32, B_), 256>>>();

    // attention: scores with fused exp + row-sum epilogue, then ctx with 1/L epilogue
    tc_gemm<M_SCORES><<<dim3(S_ / 128, S_ / 128, B_ * NH_), 256, SMEM_SZ>>>(
        (cbf*)qs_h, (cbf*)qs_l, (cbf*)ks_h, (cbf*)ks_l,
        nullptr, nullptr, nullptr, nullptr, nullptr, nullptr, nullptr, amask,
        nullptr, nullptr);
    tc_gemm<M_CTX><<<dim3(1, S_ / 128, B_ * NH_), 256, SMEM_SZ>>>(
        (cbf*)Ps_h, (cbf*)Ps_l, (cbf*)vts_h, (cbf*)vts_l,
        nullptr, (u32*)cts_h, (u32*)cts_l, nullptr, nullptr, nullptr, nullptr, nullptr,
        nullptr, nullptr);

    // O path: XA then O-MoE into slot buffer (non-atomic), then combine into out
    tc_gemm<M_XA><<<dim3(4, T_ / 128), 256, SMEM_SZ>>>(
        (cbf*)cts_h, (cbf*)cts_l, (cbf*)wcs2_h, (cbf*)wcs2_l,
        (float*)p_xao, nullptr, nullptr, nullptr, nullptr, nullptr, nullptr, nullptr,
        nullptr, nullptr);
    tc_gemm<M_MOE><<<dim3(H_ / 128, T_ / 128, E_), 256, SMEM_SZ>>>(
        (cbf*)cts_h, (cbf*)cts_l, (cbf*)obs_h, (cbf*)obs_l,
        nullptr, nullptr, nullptr, (const float*)p_xao, o_b,
        (const int*)p_list_o, (const int*)p_cnt_o, (const float*)p_ws_o,
        nullptr, nullptr);
    combine_kernel<<<(T_ * H_ / 4 + 255) / 256, 256>>>(out);
}